// round 14
// baseline (speedup 1.0000x reference)
#include <cuda_runtime.h>
#include <cstdint>

#define MAX_NODES 50000
#define LAT       100
#define NGRAPH    256
#define H2        200
#define NCLASS    55
#define D         56          // padded class dim (14 float4)
#define MAX_EDGES 800000
#define KMAX      512

typedef unsigned long long u64;

// ---------------- scratch (device globals) ---------------------------------
__device__ __align__(16) float g_bufA[MAX_NODES * D];
__device__ __align__(16) float g_bufB[MAX_NODES * D];
__device__ __align__(16) float g_inv_out[MAX_NODES];
__device__ __align__(16) float g_inv_in[MAX_NODES];
__device__ __align__(16) float g_s1[MAX_NODES];
__device__ __align__(16) int   g_off[MAX_NODES + 16];
__device__ __align__(16) int   g_cur[MAX_NODES];
__device__ __align__(16) int   g_csr[MAX_EDGES];
__device__ __align__(16) u64   g_state[64];               // decoupled-lookback states
__device__            int      g_wfdone;                  // Wfin-done counter
__device__ __align__(16) float g_T1[LAT * D];             // W2 @ Wc (padded)
__device__ __align__(16) float g_Wfin[LAT * D];           // W1 @ T1 (padded)
__device__ __align__(16) float g_Wall[KMAX * D];          // W_ext @ Wfin
__device__ __align__(16) float g_bfold[64];               // b_ext @ Wfin
__device__ __align__(16) float g_v1[64];                  // b1 @ T1
__device__ __align__(16) float g_c0[64];                  // b2 @ Wc + bc

// packed zero region: out_deg(f32) | deg_in(i32) | poolX[256*56] | poolD | cnt
#define ZR_OUTDEG 0
#define ZR_DEGIN  50000
#define ZR_POOLX  100000
#define ZR_POOLD  114336
#define ZR_CNT    114592
#define ZR_TOTAL  114848
__device__ __align__(16) float g_zregion[ZR_TOTAL];

// ---------------- f32x2 packed math helpers --------------------------------
__device__ __forceinline__ void ffma2(u64& d, u64 a, u64 b) {
    asm("fma.rn.f32x2 %0, %1, %2, %0;" : "+l"(d) : "l"(a), "l"(b));
}
__device__ __forceinline__ float2 unpack2(u64 v) {
    float2 f; asm("mov.b64 {%0, %1}, %2;" : "=f"(f.x), "=f"(f.y) : "l"(v)); return f;
}
__device__ __forceinline__ u64 swap2(u64 v) {
    float2 f = unpack2(v);
    u64 r; asm("mov.b64 %0, {%1, %2};" : "=l"(r) : "f"(f.y), "f"(f.x));
    return r;
}

// ---------------- cp.async helpers -----------------------------------------
__device__ __forceinline__ void cp_async16(uint32_t saddr, const void* gptr) {
    asm volatile("cp.async.ca.shared.global [%0], [%1], 16;"
                 :: "r"(saddr), "l"(gptr));
}
__device__ __forceinline__ void cp_commit() {
    asm volatile("cp.async.commit_group;");
}
__device__ __forceinline__ void cp_wait_all() {
    asm volatile("cp.async.wait_group 0;");
}

// ---------------- L1: prep (zero packed scratch + sync state) ---------------
__global__ void prep_kernel() {
    int i = blockIdx.x * blockDim.x + threadIdx.x;
    int stride = gridDim.x * blockDim.x;
    float4* z = (float4*)g_zregion;
    float4 zv = make_float4(0.f, 0.f, 0.f, 0.f);
    for (int t = i; t < ZR_TOTAL / 4; t += stride) z[t] = zv;
    if (i < 64) g_state[i] = 0ull;
    if (i == 64) g_wfdone = 0;
}

// ---------------- L2: degree histograms || T1 = W2 @ Wc ---------------------
#define WT_BLK 22   // ceil(100*56/256)
__global__ void fuse_deg_wT_kernel(const int* __restrict__ src,
                                   const int* __restrict__ dst, int E,
                                   const float* __restrict__ W2,
                                   const float* __restrict__ Wc) {
    if (blockIdx.x < WT_BLK) {
        int idx = blockIdx.x * 256 + threadIdx.x;
        if (idx < LAT * D) {
            int i = idx / D, j = idx - i * D;
            float a0 = 0.f, a1 = 0.f, a2 = 0.f, a3 = 0.f;
            if (j < NCLASS) {
                const float* w2r = W2 + i * H2;
#pragma unroll
                for (int k = 0; k < H2; k += 4) {
                    a0 += w2r[k]     * Wc[k * NCLASS + j];
                    a1 += w2r[k + 1] * Wc[(k + 1) * NCLASS + j];
                    a2 += w2r[k + 2] * Wc[(k + 2) * NCLASS + j];
                    a3 += w2r[k + 3] * Wc[(k + 3) * NCLASS + j];
                }
            }
            g_T1[idx] = (a0 + a1) + (a2 + a3);
        }
    } else {
        int i = (blockIdx.x - WT_BLK) * 256 + threadIdx.x;
        if (i < E) {
            float* out_deg = g_zregion + ZR_OUTDEG;
            int*   deg_in  = (int*)(g_zregion + ZR_DEGIN);
            atomicAdd(&out_deg[src[i]], 1.0f);
            atomicAdd(&deg_in[dst[i]], 1);
        }
    }
}

// ---------------- L3: single-pass scan || Wfin || Wall || biases ------------
#define WF_BLK 6
#define WA_BLK 14   // ceil(256*56/1024)
#define SCAN_BASE (WF_BLK + WA_BLK + 1)
__global__ void __launch_bounds__(1024) fuse_scan_fold_kernel(
        const int* __restrict__ gid, int n, int nb,
        const float* __restrict__ W1,
        const float* __restrict__ W_ext, int RAW,
        const float* __restrict__ b1,
        const float* __restrict__ b2,
        const float* __restrict__ Wc,
        const float* __restrict__ bc,
        const float* __restrict__ b_ext) {
    int tid = threadIdx.x;
    int b = blockIdx.x;

    if (b < WF_BLK) {
        int idx = b * 1024 + tid;
        if (idx < LAT * D) {
            int i = idx / D, j = idx - i * D;
            const float* w1r = W1 + i * LAT;
            float a0 = 0.f, a1 = 0.f, a2 = 0.f, a3 = 0.f;
#pragma unroll
            for (int k = 0; k < LAT; k += 4) {
                a0 += w1r[k]     * g_T1[k * D + j];
                a1 += w1r[k + 1] * g_T1[(k + 1) * D + j];
                a2 += w1r[k + 2] * g_T1[(k + 2) * D + j];
                a3 += w1r[k + 3] * g_T1[(k + 3) * D + j];
            }
            g_Wfin[idx] = (a0 + a1) + (a2 + a3);
        }
        __threadfence();
        __syncthreads();
        if (tid == 0) atomicAdd(&g_wfdone, 1);
        return;
    }
    if (b < WF_BLK + WA_BLK + 1) {
        if (tid == 0) {
            while (atomicAdd(&g_wfdone, 0) < WF_BLK) { }
        }
        __syncthreads();
        if (b < WF_BLK + WA_BLK) {
            __shared__ float sWf[LAT * D];
            for (int t = tid; t < LAT * D; t += 1024) sWf[t] = g_Wfin[t];
            __syncthreads();
            int idx = (b - WF_BLK) * 1024 + tid;
            if (idx < RAW * D) {
                int i = idx / D, c = idx - i * D;
                const float* wer = W_ext + i * LAT;
                float a0 = 0.f, a1 = 0.f, a2 = 0.f, a3 = 0.f;
#pragma unroll
                for (int k = 0; k < LAT; k += 4) {
                    a0 += wer[k]     * sWf[k * D + c];
                    a1 += wer[k + 1] * sWf[(k + 1) * D + c];
                    a2 += wer[k + 2] * sWf[(k + 2) * D + c];
                    a3 += wer[k + 3] * sWf[(k + 3) * D + c];
                }
                g_Wall[idx] = (a0 + a1) + (a2 + a3);
            }
        } else {
            int j = tid;
            if (j < D) {
                float v0 = 0.f, v1a = 0.f, f0 = 0.f, f1 = 0.f;
#pragma unroll
                for (int k = 0; k < LAT; k += 2) {
                    v0  += b1[k]        * g_T1[k * D + j];
                    v1a += b1[k + 1]    * g_T1[(k + 1) * D + j];
                    f0  += b_ext[k]     * g_Wfin[k * D + j];
                    f1  += b_ext[k + 1] * g_Wfin[(k + 1) * D + j];
                }
                g_v1[j] = v0 + v1a;
                g_bfold[j] = f0 + f1;
                if (j < NCLASS) {
                    float c0a = 0.f, c1 = 0.f, c2 = 0.f, c3 = 0.f;
#pragma unroll
                    for (int k = 0; k < H2; k += 4) {
                        c0a += b2[k]     * Wc[k * NCLASS + j];
                        c1  += b2[k + 1] * Wc[(k + 1) * NCLASS + j];
                        c2  += b2[k + 2] * Wc[(k + 2) * NCLASS + j];
                        c3  += b2[k + 3] * Wc[(k + 3) * NCLASS + j];
                    }
                    g_c0[j] = (c0a + c1) + (c2 + c3) + bc[j];
                }
            }
        }
        return;
    }

    // ---- scan blocks: decoupled lookback over deg_in ----
    __shared__ int wsum[32];
    __shared__ int s_prefix;
    const float* out_deg = g_zregion + ZR_OUTDEG;
    const int*   deg_in  = (const int*)(g_zregion + ZR_DEGIN);
    float* cnt = g_zregion + ZR_CNT;
    int bb = b - SCAN_BASE;
    int lane = tid & 31, warp = tid >> 5;
    int i = bb * 1024 + tid;
    int v = 0;
    if (i < n) {
        v = deg_in[i];
        float ii = rsqrtf(fmaxf((float)v, 1.0f));
        float io = rsqrtf(fmaxf(out_deg[i], 1.0f));
        g_inv_in[i]  = ii;
        g_inv_out[i] = io;
        g_s1[i]      = ii * io;
        atomicAdd(&cnt[gid[i]], 1.0f);
    }
    int s = v;
#pragma unroll
    for (int d = 1; d < 32; d <<= 1) {
        int t = __shfl_up_sync(0xffffffffu, s, d);
        if (lane >= d) s += t;
    }
    if (lane == 31) wsum[warp] = s;
    __syncthreads();
    if (warp == 0) {
        int ws = wsum[lane];
#pragma unroll
        for (int d = 1; d < 32; d <<= 1) {
            int t = __shfl_up_sync(0xffffffffu, ws, d);
            if (lane >= d) ws += t;
        }
        wsum[lane] = ws;
    }
    __syncthreads();
    int wpre = (warp > 0) ? wsum[warp - 1] : 0;
    int total = wsum[31];
    if (tid == 0) {
        int run = 0;
        if (bb == 0) {
            atomicExch(&g_state[0], (2ull << 32) | (unsigned)total);
        } else {
            atomicExch(&g_state[bb], (1ull << 32) | (unsigned)total);
            int j = bb - 1;
            while (j >= 0) {
                u64 st;
                do { st = atomicAdd(&g_state[j], 0ull); } while ((st >> 32) == 0);
                run += (int)(unsigned)st;
                if ((st >> 32) == 2ull) break;
                j--;
            }
            atomicExch(&g_state[bb], (2ull << 32) | (unsigned)(run + total));
        }
        s_prefix = run;
    }
    __syncthreads();
    int excl = s - v + wpre + s_prefix;
    if (i < n) { g_off[i] = excl; g_cur[i] = excl; }
    if (bb == nb - 1 && tid == 0) g_off[n] = s_prefix + total;
}

// ---------------- L4: GEMM0 || CSR scatter -----------------------------------
// A-tile uses XOR swizzle: 16B chunk (row>>2) stored at ((row>>2) ^ (k>>2)).
// Store banks: ((rb^q)*4 + rl) mod 32 covers all 32 -> conflict-free STS.
// Loads stay 16B-aligned; address needs 1 extra XOR per k (ALU pipe).
#define TM 128
#define KC 32
#define SAW 128                       // words per k-row (no pad needed)
#define SW 60
#define ABUF (KC * SAW)
#define WBUF (KC * SW)
#define GSMEM ((2 * ABUF + 2 * WBUF) * 4)
__global__ void __launch_bounds__(256, 3) fuse_gemm_scatter_kernel(
        const float* __restrict__ A,
        const float* __restrict__ Wn,
        const float* __restrict__ bias,
        const float* __restrict__ sout,
        float* __restrict__ C, int M, int K, int gb,
        const int* __restrict__ src, const int* __restrict__ dst, int E) {
    if (blockIdx.x >= gb) {
        int i = (blockIdx.x - gb) * 256 + threadIdx.x;
        if (i < E) {
            int p = atomicAdd(&g_cur[dst[i]], 1);
            g_csr[p] = src[i];
        }
        return;
    }
    extern __shared__ float sm[];
    float* AsB = sm;
    float* WsB = sm + 2 * ABUF;
    uint32_t wbase = (uint32_t)__cvta_generic_to_shared(WsB);

    int tid = threadIdx.x;
    int m0 = blockIdx.x * TM;
    bool worker = tid < 224;
    int ty = tid / 14;
    int tx = tid - ty * 14;
    int rb0 = ty * 2;                // row-chunk base (r0 = ty*8)
    int c0 = tx * 4;

    u64 accd[4][2], accx[4][2];
#pragma unroll
    for (int p = 0; p < 4; p++) {
        accd[p][0] = accd[p][1] = 0ull;
        accx[p][0] = accx[p][1] = 0ull;
    }

    float4 aQ[4];
    int nk = (K + KC - 1) / KC;

    auto loadW = [&](int k0, int buf) {
#pragma unroll
        for (int s = 0; s < 2; s++) {
            int idx = tid + s * 256;
            if (idx < KC * 14) {
                int kk = idx / 14, c4 = idx - kk * 14;
                int gk = k0 + kk;
                uint32_t dstp = wbase + (buf * WBUF + kk * SW + c4 * 4) * 4;
                if (gk < K) {
                    cp_async16(dstp, &Wn[(size_t)gk * D + c4 * 4]);
                } else {
                    float* d = WsB + buf * WBUF + kk * SW + c4 * 4;
                    d[0] = d[1] = d[2] = d[3] = 0.f;
                }
            }
        }
    };
    auto loadA = [&](int k0) {
#pragma unroll
        for (int s = 0; s < 4; s++) {
            int idx = tid + s * 256;
            int row = idx >> 3, q = idx & 7;
            int gr = m0 + row; if (gr >= M) gr = M - 1;
            int gk = k0 + q * 4;
            if (gk + 3 < K) {
                aQ[s] = *(const float4*)&A[(size_t)gr * K + gk];
            } else {
                aQ[s].x = (gk     < K) ? A[(size_t)gr * K + gk]     : 0.f;
                aQ[s].y = (gk + 1 < K) ? A[(size_t)gr * K + gk + 1] : 0.f;
                aQ[s].z = (gk + 2 < K) ? A[(size_t)gr * K + gk + 2] : 0.f;
                aQ[s].w = (gk + 3 < K) ? A[(size_t)gr * K + gk + 3] : 0.f;
            }
        }
    };
    auto storeA = [&](int buf) {
        float* Ab = AsB + buf * ABUF;
#pragma unroll
        for (int s = 0; s < 4; s++) {
            int idx = tid + s * 256;
            int row = idx >> 3, q = idx & 7;
            int rb = row >> 2, rl = row & 3;
            int ch = rb ^ q;                       // swizzled 16B chunk
            int a = (q * 4) * SAW + ch * 4 + rl;   // k = 4q+j, j adds SAW each
            Ab[a]           = aQ[s].x;
            Ab[a + SAW]     = aQ[s].y;
            Ab[a + 2 * SAW] = aQ[s].z;
            Ab[a + 3 * SAW] = aQ[s].w;
        }
    };

    loadW(0, 0);
    cp_commit();
    loadA(0);
    storeA(0);
    cp_wait_all();
    __syncthreads();

    for (int ch = 0; ch < nk; ch++) {
        int buf = ch & 1;
        if (ch + 1 < nk) {
            loadA((ch + 1) * KC);
            loadW((ch + 1) * KC, buf ^ 1);
            cp_commit();
        }
        if (worker) {
            const float* Ab = AsB + buf * ABUF;
            const float* Wb = WsB + buf * WBUF;
#pragma unroll 4
            for (int k = 0; k < KC; k++) {
                int qk = k >> 2;
                const float* Ak = Ab + k * SAW;
                ulonglong2 a01 = *(const ulonglong2*)(Ak + ((rb0 ^ qk) << 2));
                ulonglong2 a23 = *(const ulonglong2*)(Ak + (((rb0 + 1) ^ qk) << 2));
                ulonglong2 w   = *(const ulonglong2*)(Wb + k * SW + c0);
                u64 wxs = swap2(w.x);
                u64 wys = swap2(w.y);
                ffma2(accd[0][0], a01.x, w.x);  ffma2(accx[0][0], a01.x, wxs);
                ffma2(accd[0][1], a01.x, w.y);  ffma2(accx[0][1], a01.x, wys);
                ffma2(accd[1][0], a01.y, w.x);  ffma2(accx[1][0], a01.y, wxs);
                ffma2(accd[1][1], a01.y, w.y);  ffma2(accx[1][1], a01.y, wys);
                ffma2(accd[2][0], a23.x, w.x);  ffma2(accx[2][0], a23.x, wxs);
                ffma2(accd[2][1], a23.x, w.y);  ffma2(accx[2][1], a23.x, wys);
                ffma2(accd[3][0], a23.y, w.x);  ffma2(accx[3][0], a23.y, wxs);
                ffma2(accd[3][1], a23.y, w.y);  ffma2(accx[3][1], a23.y, wys);
            }
        }
        if (ch + 1 < nk) {
            storeA(buf ^ 1);
            cp_wait_all();
            __syncthreads();
        }
    }

    if (worker) {
        float4 bv = *(const float4*)&bias[c0];
        int r0 = rb0 * 4;
#pragma unroll
        for (int p = 0; p < 4; p++) {
            float2 d0 = unpack2(accd[p][0]);
            float2 x0 = unpack2(accx[p][0]);
            float2 d1 = unpack2(accd[p][1]);
            float2 x1 = unpack2(accx[p][1]);
            int row = m0 + r0 + 2 * p;
            if (row < M) {
                float so = sout[row];
                float4 v = make_float4((d0.x + bv.x) * so, (x0.x + bv.y) * so,
                                       (d1.x + bv.z) * so, (x1.x + bv.w) * so);
                *(float4*)&C[(size_t)row * D + c0] = v;
            }
            if (row + 1 < M) {
                float so = sout[row + 1];
                float4 v = make_float4((x0.y + bv.x) * so, (d0.y + bv.y) * so,
                                       (x1.y + bv.z) * so, (d1.y + bv.w) * so);
                *(float4*)&C[(size_t)(row + 1) * D + c0] = v;
            }
        }
    }
}

// ---------------- L5/L6: CSR propagation (unroll 8, half-warp per node) -----
template <bool POOL>
__global__ void prop_csr_kernel(const float4* __restrict__ xs,
                                float4* __restrict__ agg,
                                const float* __restrict__ scale,
                                const int* __restrict__ gid, int n) {
    int node = (blockIdx.x * blockDim.x + threadIdx.x) >> 4;
    int l = threadIdx.x & 15;
    if (node >= n) return;
    int b = g_off[node], e = g_off[node + 1];
    bool act = l < 14;
    bool dt  = (!POOL) && (l == 14);
    float4 a0 = make_float4(0.f, 0.f, 0.f, 0.f);
    float4 a1 = a0, a2 = a0, a3 = a0;
    float sd = 0.f;
    unsigned base = (unsigned)l;
    int k = b;
    for (; k + 8 <= e; k += 8) {
        int s0 = g_csr[k],     s1 = g_csr[k + 1], s2 = g_csr[k + 2], s3 = g_csr[k + 3];
        int s4 = g_csr[k + 4], s5 = g_csr[k + 5], s6 = g_csr[k + 6], s7 = g_csr[k + 7];
        if (act) {
            float4 v0 = xs[(unsigned)s0 * 14u + base];
            float4 v1 = xs[(unsigned)s1 * 14u + base];
            float4 v2 = xs[(unsigned)s2 * 14u + base];
            float4 v3 = xs[(unsigned)s3 * 14u + base];
            float4 v4 = xs[(unsigned)s4 * 14u + base];
            float4 v5 = xs[(unsigned)s5 * 14u + base];
            float4 v6 = xs[(unsigned)s6 * 14u + base];
            float4 v7 = xs[(unsigned)s7 * 14u + base];
            a0.x += v0.x + v4.x; a0.y += v0.y + v4.y; a0.z += v0.z + v4.z; a0.w += v0.w + v4.w;
            a1.x += v1.x + v5.x; a1.y += v1.y + v5.y; a1.z += v1.z + v5.z; a1.w += v1.w + v5.w;
            a2.x += v2.x + v6.x; a2.y += v2.y + v6.y; a2.z += v2.z + v6.z; a2.w += v2.w + v6.w;
            a3.x += v3.x + v7.x; a3.y += v3.y + v7.y; a3.z += v3.z + v7.z; a3.w += v3.w + v7.w;
        } else if (dt) {
            sd += g_inv_out[s0] + g_inv_out[s1] + g_inv_out[s2] + g_inv_out[s3]
                + g_inv_out[s4] + g_inv_out[s5] + g_inv_out[s6] + g_inv_out[s7];
        }
    }
    for (; k + 2 <= e; k += 2) {
        int s0 = g_csr[k], s1 = g_csr[k + 1];
        if (act) {
            float4 v0 = xs[(unsigned)s0 * 14u + base];
            float4 v1 = xs[(unsigned)s1 * 14u + base];
            a0.x += v0.x; a0.y += v0.y; a0.z += v0.z; a0.w += v0.w;
            a1.x += v1.x; a1.y += v1.y; a1.z += v1.z; a1.w += v1.w;
        } else if (dt) {
            sd += g_inv_out[s0] + g_inv_out[s1];
        }
    }
    if (k < e) {
        int s0 = g_csr[k];
        if (act) {
            float4 v0 = xs[(unsigned)s0 * 14u + base];
            a0.x += v0.x; a0.y += v0.y; a0.z += v0.z; a0.w += v0.w;
        } else if (dt) {
            sd += g_inv_out[s0];
        }
    }
    if (act) {
        float sc = scale[node];
        float x = (a0.x + a1.x + a2.x + a3.x) * sc;
        float y = (a0.y + a1.y + a2.y + a3.y) * sc;
        float z = (a0.z + a1.z + a2.z + a3.z) * sc;
        float w = (a0.w + a1.w + a2.w + a3.w) * sc;
        if (!POOL) {
            agg[(unsigned)node * 14u + base] = make_float4(x, y, z, w);
        } else {
            float* poolX = g_zregion + ZR_POOLX;
            float* p = poolX + (unsigned)gid[node] * D + base * 4u;
            asm volatile("red.global.add.v4.f32 [%0], {%1,%2,%3,%4};"
                         :: "l"(p), "f"(x), "f"(y), "f"(z), "f"(w)
                         : "memory");
        }
    } else if (dt) {
        float* poolD = g_zregion + ZR_POOLD;
        atomicAdd(&poolD[gid[node]], sd * g_inv_in[node]);
    }
}

// ---------------- L7: final --------------------------------------------------
__global__ void final_kernel(float* __restrict__ out) {
    const float* poolX = g_zregion + ZR_POOLX;
    const float* poolD = g_zregion + ZR_POOLD;
    const float* cnt   = g_zregion + ZR_CNT;
    int g = blockIdx.x, tid = threadIdx.x;
    if (tid < NCLASS) {
        float invc = 1.0f / fmaxf(cnt[g], 1.0f);
        out[g * NCLASS + tid] = poolX[g * D + tid] * invc
                              + poolD[g] * invc * g_v1[tid]
                              + g_c0[tid];
    }
}

// ---------------- launch ---------------------------------------------------
extern "C" void kernel_launch(void* const* d_in, const int* in_sizes, int n_in,
                              void* d_out, int out_size) {
    const float* fsnet = (const float*)d_in[0];
    const int*   src   = (const int*)d_in[1];
    const int*   dst   = (const int*)d_in[2];
    const int*   gid   = (const int*)d_in[3];
    const float* W_ext = (const float*)d_in[4];
    const float* b_ext = (const float*)d_in[5];
    const float* W1    = (const float*)d_in[6];
    const float* b1    = (const float*)d_in[7];
    const float* W2    = (const float*)d_in[8];
    const float* b2    = (const float*)d_in[9];
    const float* Wc    = (const float*)d_in[10];
    const float* bc    = (const float*)d_in[11];
    float* out = (float*)d_out;

    int n   = in_sizes[3];
    int E   = in_sizes[1];
    int RAW = in_sizes[4] / LAT;

    float *bufA, *bufB, *inv_out, *inv_in, *s1, *wall, *bfold;
    cudaGetSymbolAddress((void**)&bufA,    g_bufA);
    cudaGetSymbolAddress((void**)&bufB,    g_bufB);
    cudaGetSymbolAddress((void**)&inv_out, g_inv_out);
    cudaGetSymbolAddress((void**)&inv_in,  g_inv_in);
    cudaGetSymbolAddress((void**)&s1,      g_s1);
    cudaGetSymbolAddress((void**)&wall,    g_Wall);
    cudaGetSymbolAddress((void**)&bfold,   g_bfold);

    cudaFuncSetAttribute(fuse_gemm_scatter_kernel,
                         cudaFuncAttributeMaxDynamicSharedMemorySize, GSMEM);

    int nb = (n + 1023) / 1024;          // scan blocks
    int eb = (E + 255) / 256;            // edge blocks
    int gb = (n + TM - 1) / TM;          // gemm blocks

    // L1: zero packed scratch + lookback state
    prep_kernel<<<148, 256>>>();
    // L2: degree histograms || T1 = W2@Wc
    fuse_deg_wT_kernel<<<WT_BLK + eb, 256>>>(src, dst, E, W2, Wc);
    // L3: single-pass scan || Wfin || Wall || biases (flag-ordered)
    fuse_scan_fold_kernel<<<SCAN_BASE + nb, 1024>>>(
        gid, n, nb, W1, W_ext, RAW, b1, b2, Wc, bc, b_ext);
    // L4: GEMM0 || CSR scatter
    fuse_gemm_scatter_kernel<<<gb + eb, 256, GSMEM>>>(
        fsnet, wall, bfold, inv_out, bufA, n, RAW, gb, src, dst, E);
    // L5: prop1 (+ fused dtilde): bufB = P(z0) * s1
    int pblocks = (n * 16 + 255) / 256;
    prop_csr_kernel<false><<<pblocks, 256>>>((const float4*)bufA, (float4*)bufB, s1, gid, n);
    // L6: prop2 fused with graph pooling
    prop_csr_kernel<true><<<pblocks, 256>>>((const float4*)bufB, nullptr, inv_in, gid, n);
    // L7: out = poolX/cnt + (poolD/cnt)*v1 + c0
    final_kernel<<<NGRAPH, 64>>>(out);
}

// round 15
// speedup vs baseline: 1.0593x; 1.0593x over previous
#include <cuda_runtime.h>
#include <cstdint>

#define MAX_NODES 50000
#define LAT       100
#define NGRAPH    256
#define H2        200
#define NCLASS    55
#define D         56          // class dim (padded to 56 for 14 float4 chunks)
#define DP        64          // feature row stride in floats (256B, line-aligned)
#define MAX_EDGES 800000
#define KMAX      512

typedef unsigned long long u64;

// ---------------- scratch (device globals) ---------------------------------
__device__ __align__(256) float g_bufA[MAX_NODES * DP];
__device__ __align__(256) float g_bufB[MAX_NODES * DP];
__device__ __align__(16) float g_inv_out[MAX_NODES];
__device__ __align__(16) float g_inv_in[MAX_NODES];
__device__ __align__(16) float g_s1[MAX_NODES];
__device__ __align__(16) int   g_off[MAX_NODES + 16];
__device__ __align__(16) int   g_cur[MAX_NODES];
__device__ __align__(16) int   g_csr[MAX_EDGES];
__device__ __align__(16) u64   g_state[64];               // decoupled-lookback states
__device__            int      g_wfdone;                  // Wfin-done counter
__device__ __align__(16) float g_T1[LAT * D];             // W2 @ Wc (padded)
__device__ __align__(16) float g_Wfin[LAT * D];           // W1 @ T1 (padded)
__device__ __align__(16) float g_Wall[KMAX * D];          // W_ext @ Wfin
__device__ __align__(16) float g_bfold[64];               // b_ext @ Wfin
__device__ __align__(16) float g_v1[64];                  // b1 @ T1
__device__ __align__(16) float g_c0[64];                  // b2 @ Wc + bc

// packed zero region: out_deg(f32) | deg_in(i32) | poolX[256*56] | poolD | cnt
#define ZR_OUTDEG 0
#define ZR_DEGIN  50000
#define ZR_POOLX  100000
#define ZR_POOLD  114336
#define ZR_CNT    114592
#define ZR_TOTAL  114848
__device__ __align__(16) float g_zregion[ZR_TOTAL];

// ---------------- f32x2 packed math helpers --------------------------------
__device__ __forceinline__ void ffma2(u64& d, u64 a, u64 b) {
    asm("fma.rn.f32x2 %0, %1, %2, %0;" : "+l"(d) : "l"(a), "l"(b));
}
__device__ __forceinline__ float2 unpack2(u64 v) {
    float2 f; asm("mov.b64 {%0, %1}, %2;" : "=f"(f.x), "=f"(f.y) : "l"(v)); return f;
}
__device__ __forceinline__ u64 swap2(u64 v) {
    float2 f = unpack2(v);
    u64 r; asm("mov.b64 %0, {%1, %2};" : "=l"(r) : "f"(f.y), "f"(f.x));
    return r;
}

// ---------------- cp.async helpers -----------------------------------------
__device__ __forceinline__ void cp_async16(uint32_t saddr, const void* gptr) {
    asm volatile("cp.async.ca.shared.global [%0], [%1], 16;"
                 :: "r"(saddr), "l"(gptr));
}
__device__ __forceinline__ void cp_commit() {
    asm volatile("cp.async.commit_group;");
}
__device__ __forceinline__ void cp_wait_all() {
    asm volatile("cp.async.wait_group 0;");
}

// ---------------- L1: prep (zero packed scratch + sync state) ---------------
__global__ void prep_kernel() {
    int i = blockIdx.x * blockDim.x + threadIdx.x;
    int stride = gridDim.x * blockDim.x;
    float4* z = (float4*)g_zregion;
    float4 zv = make_float4(0.f, 0.f, 0.f, 0.f);
    for (int t = i; t < ZR_TOTAL / 4; t += stride) z[t] = zv;
    if (i < 64) g_state[i] = 0ull;
    if (i == 64) g_wfdone = 0;
}

// ---------------- L2: degree histograms || T1 = W2 @ Wc ---------------------
#define WT_BLK 22   // ceil(100*56/256)
__global__ void fuse_deg_wT_kernel(const int* __restrict__ src,
                                   const int* __restrict__ dst, int E,
                                   const float* __restrict__ W2,
                                   const float* __restrict__ Wc) {
    if (blockIdx.x < WT_BLK) {
        int idx = blockIdx.x * 256 + threadIdx.x;
        if (idx < LAT * D) {
            int i = idx / D, j = idx - i * D;
            float a0 = 0.f, a1 = 0.f, a2 = 0.f, a3 = 0.f;
            if (j < NCLASS) {
                const float* w2r = W2 + i * H2;
#pragma unroll
                for (int k = 0; k < H2; k += 4) {
                    a0 += w2r[k]     * Wc[k * NCLASS + j];
                    a1 += w2r[k + 1] * Wc[(k + 1) * NCLASS + j];
                    a2 += w2r[k + 2] * Wc[(k + 2) * NCLASS + j];
                    a3 += w2r[k + 3] * Wc[(k + 3) * NCLASS + j];
                }
            }
            g_T1[idx] = (a0 + a1) + (a2 + a3);
        }
    } else {
        int i = (blockIdx.x - WT_BLK) * 256 + threadIdx.x;
        if (i < E) {
            float* out_deg = g_zregion + ZR_OUTDEG;
            int*   deg_in  = (int*)(g_zregion + ZR_DEGIN);
            atomicAdd(&out_deg[src[i]], 1.0f);
            atomicAdd(&deg_in[dst[i]], 1);
        }
    }
}

// ---------------- L3: single-pass scan || Wfin || Wall || biases ------------
#define WF_BLK 6
#define WA_BLK 14   // ceil(256*56/1024)
#define SCAN_BASE (WF_BLK + WA_BLK + 1)
__global__ void __launch_bounds__(1024) fuse_scan_fold_kernel(
        const int* __restrict__ gid, int n, int nb,
        const float* __restrict__ W1,
        const float* __restrict__ W_ext, int RAW,
        const float* __restrict__ b1,
        const float* __restrict__ b2,
        const float* __restrict__ Wc,
        const float* __restrict__ bc,
        const float* __restrict__ b_ext) {
    int tid = threadIdx.x;
    int b = blockIdx.x;

    if (b < WF_BLK) {
        int idx = b * 1024 + tid;
        if (idx < LAT * D) {
            int i = idx / D, j = idx - i * D;
            const float* w1r = W1 + i * LAT;
            float a0 = 0.f, a1 = 0.f, a2 = 0.f, a3 = 0.f;
#pragma unroll
            for (int k = 0; k < LAT; k += 4) {
                a0 += w1r[k]     * g_T1[k * D + j];
                a1 += w1r[k + 1] * g_T1[(k + 1) * D + j];
                a2 += w1r[k + 2] * g_T1[(k + 2) * D + j];
                a3 += w1r[k + 3] * g_T1[(k + 3) * D + j];
            }
            g_Wfin[idx] = (a0 + a1) + (a2 + a3);
        }
        __threadfence();
        __syncthreads();
        if (tid == 0) atomicAdd(&g_wfdone, 1);
        return;
    }
    if (b < WF_BLK + WA_BLK + 1) {
        if (tid == 0) {
            while (atomicAdd(&g_wfdone, 0) < WF_BLK) { }
        }
        __syncthreads();
        if (b < WF_BLK + WA_BLK) {
            __shared__ float sWf[LAT * D];
            for (int t = tid; t < LAT * D; t += 1024) sWf[t] = g_Wfin[t];
            __syncthreads();
            int idx = (b - WF_BLK) * 1024 + tid;
            if (idx < RAW * D) {
                int i = idx / D, c = idx - i * D;
                const float* wer = W_ext + i * LAT;
                float a0 = 0.f, a1 = 0.f, a2 = 0.f, a3 = 0.f;
#pragma unroll
                for (int k = 0; k < LAT; k += 4) {
                    a0 += wer[k]     * sWf[k * D + c];
                    a1 += wer[k + 1] * sWf[(k + 1) * D + c];
                    a2 += wer[k + 2] * sWf[(k + 2) * D + c];
                    a3 += wer[k + 3] * sWf[(k + 3) * D + c];
                }
                g_Wall[idx] = (a0 + a1) + (a2 + a3);
            }
        } else {
            int j = tid;
            if (j < D) {
                float v0 = 0.f, v1a = 0.f, f0 = 0.f, f1 = 0.f;
#pragma unroll
                for (int k = 0; k < LAT; k += 2) {
                    v0  += b1[k]        * g_T1[k * D + j];
                    v1a += b1[k + 1]    * g_T1[(k + 1) * D + j];
                    f0  += b_ext[k]     * g_Wfin[k * D + j];
                    f1  += b_ext[k + 1] * g_Wfin[(k + 1) * D + j];
                }
                g_v1[j] = v0 + v1a;
                g_bfold[j] = f0 + f1;
                if (j < NCLASS) {
                    float c0a = 0.f, c1 = 0.f, c2 = 0.f, c3 = 0.f;
#pragma unroll
                    for (int k = 0; k < H2; k += 4) {
                        c0a += b2[k]     * Wc[k * NCLASS + j];
                        c1  += b2[k + 1] * Wc[(k + 1) * NCLASS + j];
                        c2  += b2[k + 2] * Wc[(k + 2) * NCLASS + j];
                        c3  += b2[k + 3] * Wc[(k + 3) * NCLASS + j];
                    }
                    g_c0[j] = (c0a + c1) + (c2 + c3) + bc[j];
                }
            }
        }
        return;
    }

    // ---- scan blocks: decoupled lookback over deg_in ----
    __shared__ int wsum[32];
    __shared__ int s_prefix;
    const float* out_deg = g_zregion + ZR_OUTDEG;
    const int*   deg_in  = (const int*)(g_zregion + ZR_DEGIN);
    float* cnt = g_zregion + ZR_CNT;
    int bb = b - SCAN_BASE;
    int lane = tid & 31, warp = tid >> 5;
    int i = bb * 1024 + tid;
    int v = 0;
    if (i < n) {
        v = deg_in[i];
        float ii = rsqrtf(fmaxf((float)v, 1.0f));
        float io = rsqrtf(fmaxf(out_deg[i], 1.0f));
        g_inv_in[i]  = ii;
        g_inv_out[i] = io;
        g_s1[i]      = ii * io;
        atomicAdd(&cnt[gid[i]], 1.0f);
    }
    int s = v;
#pragma unroll
    for (int d = 1; d < 32; d <<= 1) {
        int t = __shfl_up_sync(0xffffffffu, s, d);
        if (lane >= d) s += t;
    }
    if (lane == 31) wsum[warp] = s;
    __syncthreads();
    if (warp == 0) {
        int ws = wsum[lane];
#pragma unroll
        for (int d = 1; d < 32; d <<= 1) {
            int t = __shfl_up_sync(0xffffffffu, ws, d);
            if (lane >= d) ws += t;
        }
        wsum[lane] = ws;
    }
    __syncthreads();
    int wpre = (warp > 0) ? wsum[warp - 1] : 0;
    int total = wsum[31];
    if (tid == 0) {
        int run = 0;
        if (bb == 0) {
            atomicExch(&g_state[0], (2ull << 32) | (unsigned)total);
        } else {
            atomicExch(&g_state[bb], (1ull << 32) | (unsigned)total);
            int j = bb - 1;
            while (j >= 0) {
                u64 st;
                do { st = atomicAdd(&g_state[j], 0ull); } while ((st >> 32) == 0);
                run += (int)(unsigned)st;
                if ((st >> 32) == 2ull) break;
                j--;
            }
            atomicExch(&g_state[bb], (2ull << 32) | (unsigned)(run + total));
        }
        s_prefix = run;
    }
    __syncthreads();
    int excl = s - v + wpre + s_prefix;
    if (i < n) { g_off[i] = excl; g_cur[i] = excl; }
    if (bb == nb - 1 && tid == 0) g_off[n] = s_prefix + total;
}

// ---------------- L4: GEMM0 || CSR scatter (round-13 core) ------------------
#define TM 128
#define KC 32
#define SA 132
#define SW 60
#define ABUF (KC * SA)
#define WBUF (KC * SW)
#define GSMEM ((2 * ABUF + 2 * WBUF) * 4)
__global__ void __launch_bounds__(256, 3) fuse_gemm_scatter_kernel(
        const float* __restrict__ A,
        const float* __restrict__ Wn,
        const float* __restrict__ bias,
        const float* __restrict__ sout,
        float* __restrict__ C, int M, int K, int gb,
        const int* __restrict__ src, const int* __restrict__ dst, int E) {
    if (blockIdx.x >= gb) {
        int i = (blockIdx.x - gb) * 256 + threadIdx.x;
        if (i < E) {
            int p = atomicAdd(&g_cur[dst[i]], 1);
            g_csr[p] = src[i];
        }
        return;
    }
    extern __shared__ float sm[];
    float* AsB = sm;
    float* WsB = sm + 2 * ABUF;
    uint32_t wbase = (uint32_t)__cvta_generic_to_shared(WsB);

    int tid = threadIdx.x;
    int m0 = blockIdx.x * TM;
    bool worker = tid < 224;
    int ty = tid / 14;
    int tx = tid - ty * 14;
    int r0 = ty * 8;
    int c0 = tx * 4;

    u64 accd[4][2], accx[4][2];
#pragma unroll
    for (int p = 0; p < 4; p++) {
        accd[p][0] = accd[p][1] = 0ull;
        accx[p][0] = accx[p][1] = 0ull;
    }

    float4 aQ[4];
    int nk = (K + KC - 1) / KC;

    auto loadW = [&](int k0, int buf) {
#pragma unroll
        for (int s = 0; s < 2; s++) {
            int idx = tid + s * 256;
            if (idx < KC * 14) {
                int kk = idx / 14, c4 = idx - kk * 14;
                int gk = k0 + kk;
                uint32_t dstp = wbase + (buf * WBUF + kk * SW + c4 * 4) * 4;
                if (gk < K) {
                    cp_async16(dstp, &Wn[(size_t)gk * D + c4 * 4]);
                } else {
                    float* d = WsB + buf * WBUF + kk * SW + c4 * 4;
                    d[0] = d[1] = d[2] = d[3] = 0.f;
                }
            }
        }
    };
    auto loadA = [&](int k0) {
#pragma unroll
        for (int s = 0; s < 4; s++) {
            int idx = tid + s * 256;
            int row = idx >> 3, q = idx & 7;
            int gr = m0 + row; if (gr >= M) gr = M - 1;
            int gk = k0 + q * 4;
            if (gk + 3 < K) {
                aQ[s] = *(const float4*)&A[(size_t)gr * K + gk];
            } else {
                aQ[s].x = (gk     < K) ? A[(size_t)gr * K + gk]     : 0.f;
                aQ[s].y = (gk + 1 < K) ? A[(size_t)gr * K + gk + 1] : 0.f;
                aQ[s].z = (gk + 2 < K) ? A[(size_t)gr * K + gk + 2] : 0.f;
                aQ[s].w = (gk + 3 < K) ? A[(size_t)gr * K + gk + 3] : 0.f;
            }
        }
    };
    auto storeA = [&](int buf) {
        float* Ab = AsB + buf * ABUF;
#pragma unroll
        for (int s = 0; s < 4; s++) {
            int idx = tid + s * 256;
            int row = idx >> 3, q = idx & 7;
            float* dstp = Ab + (q * 4) * SA + row;
            dstp[0] = aQ[s].x; dstp[SA] = aQ[s].y; dstp[2 * SA] = aQ[s].z; dstp[3 * SA] = aQ[s].w;
        }
    };

    loadW(0, 0);
    cp_commit();
    loadA(0);
    storeA(0);
    cp_wait_all();
    __syncthreads();

    for (int ch = 0; ch < nk; ch++) {
        int buf = ch & 1;
        if (ch + 1 < nk) {
            loadA((ch + 1) * KC);
            loadW((ch + 1) * KC, buf ^ 1);
            cp_commit();
        }
        if (worker) {
            const float* Ab = AsB + buf * ABUF;
            const float* Wb = WsB + buf * WBUF;
#pragma unroll 4
            for (int k = 0; k < KC; k++) {
                ulonglong2 a01 = *(const ulonglong2*)(Ab + k * SA + r0);
                ulonglong2 a23 = *(const ulonglong2*)(Ab + k * SA + r0 + 4);
                ulonglong2 w   = *(const ulonglong2*)(Wb + k * SW + c0);
                u64 wxs = swap2(w.x);
                u64 wys = swap2(w.y);
                ffma2(accd[0][0], a01.x, w.x);  ffma2(accx[0][0], a01.x, wxs);
                ffma2(accd[0][1], a01.x, w.y);  ffma2(accx[0][1], a01.x, wys);
                ffma2(accd[1][0], a01.y, w.x);  ffma2(accx[1][0], a01.y, wxs);
                ffma2(accd[1][1], a01.y, w.y);  ffma2(accx[1][1], a01.y, wys);
                ffma2(accd[2][0], a23.x, w.x);  ffma2(accx[2][0], a23.x, wxs);
                ffma2(accd[2][1], a23.x, w.y);  ffma2(accx[2][1], a23.x, wys);
                ffma2(accd[3][0], a23.y, w.x);  ffma2(accx[3][0], a23.y, wxs);
                ffma2(accd[3][1], a23.y, w.y);  ffma2(accx[3][1], a23.y, wys);
            }
        }
        if (ch + 1 < nk) {
            storeA(buf ^ 1);
            cp_wait_all();
            __syncthreads();
        }
    }

    if (worker) {
        float4 bv = *(const float4*)&bias[c0];
#pragma unroll
        for (int p = 0; p < 4; p++) {
            float2 d0 = unpack2(accd[p][0]);
            float2 x0 = unpack2(accx[p][0]);
            float2 d1 = unpack2(accd[p][1]);
            float2 x1 = unpack2(accx[p][1]);
            int row = m0 + r0 + 2 * p;
            if (row < M) {
                float so = sout[row];
                float4 v = make_float4((d0.x + bv.x) * so, (x0.x + bv.y) * so,
                                       (d1.x + bv.z) * so, (x1.x + bv.w) * so);
                *(float4*)&C[(size_t)row * DP + c0] = v;
            }
            if (row + 1 < M) {
                float so = sout[row + 1];
                float4 v = make_float4((x0.y + bv.x) * so, (d0.y + bv.y) * so,
                                       (x1.y + bv.z) * so, (d1.y + bv.w) * so);
                *(float4*)&C[(size_t)(row + 1) * DP + c0] = v;
            }
        }
    }
}

// ---------------- L5/L6: CSR propagation (256B-aligned rows) ----------------
// Rows strided DP=64 floats (16 chunks); chunks 0..13 carry data, 14-15 pad.
// Each edge gather = exactly 2 aligned 128B lines.
template <bool POOL>
__global__ void prop_csr_kernel(const float4* __restrict__ xs,
                                float4* __restrict__ agg,
                                const float* __restrict__ scale,
                                const int* __restrict__ gid, int n) {
    int node = (blockIdx.x * blockDim.x + threadIdx.x) >> 4;
    int l = threadIdx.x & 15;
    if (node >= n) return;
    int b = g_off[node], e = g_off[node + 1];
    bool act = l < 14;
    bool dt  = (!POOL) && (l == 14);
    float4 a0 = make_float4(0.f, 0.f, 0.f, 0.f);
    float4 a1 = a0, a2 = a0, a3 = a0;
    float sd = 0.f;
    unsigned base = (unsigned)l;
    int k = b;
    for (; k + 4 <= e; k += 4) {
        int s0 = g_csr[k], s1 = g_csr[k + 1], s2 = g_csr[k + 2], s3 = g_csr[k + 3];
        if (act) {
            float4 v0 = xs[(unsigned)s0 * 16u + base];
            float4 v1 = xs[(unsigned)s1 * 16u + base];
            float4 v2 = xs[(unsigned)s2 * 16u + base];
            float4 v3 = xs[(unsigned)s3 * 16u + base];
            a0.x += v0.x; a0.y += v0.y; a0.z += v0.z; a0.w += v0.w;
            a1.x += v1.x; a1.y += v1.y; a1.z += v1.z; a1.w += v1.w;
            a2.x += v2.x; a2.y += v2.y; a2.z += v2.z; a2.w += v2.w;
            a3.x += v3.x; a3.y += v3.y; a3.z += v3.z; a3.w += v3.w;
        } else if (dt) {
            sd += g_inv_out[s0] + g_inv_out[s1] + g_inv_out[s2] + g_inv_out[s3];
        }
    }
    for (; k < e; k++) {
        int s0 = g_csr[k];
        if (act) {
            float4 v0 = xs[(unsigned)s0 * 16u + base];
            a0.x += v0.x; a0.y += v0.y; a0.z += v0.z; a0.w += v0.w;
        } else if (dt) {
            sd += g_inv_out[s0];
        }
    }
    if (act) {
        float sc = scale[node];
        float x = (a0.x + a1.x + a2.x + a3.x) * sc;
        float y = (a0.y + a1.y + a2.y + a3.y) * sc;
        float z = (a0.z + a1.z + a2.z + a3.z) * sc;
        float w = (a0.w + a1.w + a2.w + a3.w) * sc;
        if (!POOL) {
            agg[(unsigned)node * 16u + base] = make_float4(x, y, z, w);
        } else {
            float* poolX = g_zregion + ZR_POOLX;
            float* p = poolX + (unsigned)gid[node] * D + base * 4u;
            asm volatile("red.global.add.v4.f32 [%0], {%1,%2,%3,%4};"
                         :: "l"(p), "f"(x), "f"(y), "f"(z), "f"(w)
                         : "memory");
        }
    } else if (dt) {
        float* poolD = g_zregion + ZR_POOLD;
        atomicAdd(&poolD[gid[node]], sd * g_inv_in[node]);
    }
}

// ---------------- L7: final --------------------------------------------------
__global__ void final_kernel(float* __restrict__ out) {
    const float* poolX = g_zregion + ZR_POOLX;
    const float* poolD = g_zregion + ZR_POOLD;
    const float* cnt   = g_zregion + ZR_CNT;
    int g = blockIdx.x, tid = threadIdx.x;
    if (tid < NCLASS) {
        float invc = 1.0f / fmaxf(cnt[g], 1.0f);
        out[g * NCLASS + tid] = poolX[g * D + tid] * invc
                              + poolD[g] * invc * g_v1[tid]
                              + g_c0[tid];
    }
}

// ---------------- launch ---------------------------------------------------
extern "C" void kernel_launch(void* const* d_in, const int* in_sizes, int n_in,
                              void* d_out, int out_size) {
    const float* fsnet = (const float*)d_in[0];
    const int*   src   = (const int*)d_in[1];
    const int*   dst   = (const int*)d_in[2];
    const int*   gid   = (const int*)d_in[3];
    const float* W_ext = (const float*)d_in[4];
    const float* b_ext = (const float*)d_in[5];
    const float* W1    = (const float*)d_in[6];
    const float* b1    = (const float*)d_in[7];
    const float* W2    = (const float*)d_in[8];
    const float* b2    = (const float*)d_in[9];
    const float* Wc    = (const float*)d_in[10];
    const float* bc    = (const float*)d_in[11];
    float* out = (float*)d_out;

    int n   = in_sizes[3];
    int E   = in_sizes[1];
    int RAW = in_sizes[4] / LAT;

    float *bufA, *bufB, *inv_out, *inv_in, *s1, *wall, *bfold;
    cudaGetSymbolAddress((void**)&bufA,    g_bufA);
    cudaGetSymbolAddress((void**)&bufB,    g_bufB);
    cudaGetSymbolAddress((void**)&inv_out, g_inv_out);
    cudaGetSymbolAddress((void**)&inv_in,  g_inv_in);
    cudaGetSymbolAddress((void**)&s1,      g_s1);
    cudaGetSymbolAddress((void**)&wall,    g_Wall);
    cudaGetSymbolAddress((void**)&bfold,   g_bfold);

    cudaFuncSetAttribute(fuse_gemm_scatter_kernel,
                         cudaFuncAttributeMaxDynamicSharedMemorySize, GSMEM);

    int nb = (n + 1023) / 1024;          // scan blocks
    int eb = (E + 255) / 256;            // edge blocks
    int gb = (n + TM - 1) / TM;          // gemm blocks

    // L1: zero packed scratch + lookback state
    prep_kernel<<<148, 256>>>();
    // L2: degree histograms || T1 = W2@Wc
    fuse_deg_wT_kernel<<<WT_BLK + eb, 256>>>(src, dst, E, W2, Wc);
    // L3: single-pass scan || Wfin || Wall || biases (flag-ordered)
    fuse_scan_fold_kernel<<<SCAN_BASE + nb, 1024>>>(
        gid, n, nb, W1, W_ext, RAW, b1, b2, Wc, bc, b_ext);
    // L4: GEMM0 || CSR scatter
    fuse_gemm_scatter_kernel<<<gb + eb, 256, GSMEM>>>(
        fsnet, wall, bfold, inv_out, bufA, n, RAW, gb, src, dst, E);
    // L5: prop1 (+ fused dtilde): bufB = P(z0) * s1
    int pblocks = (n * 16 + 255) / 256;
    prop_csr_kernel<false><<<pblocks, 256>>>((const float4*)bufA, (float4*)bufB, s1, gid, n);
    // L6: prop2 fused with graph pooling
    prop_csr_kernel<true><<<pblocks, 256>>>((const float4*)bufB, nullptr, inv_in, gid, n);
    // L7: out = poolX/cnt + (poolD/cnt)*v1 + c0
    final_kernel<<<NGRAPH, 64>>>(out);
}

// round 16
// speedup vs baseline: 1.0751x; 1.0149x over previous
#include <cuda_runtime.h>
#include <cstdint>

#define MAX_NODES 50000
#define LAT       100
#define NGRAPH    256
#define H2        200
#define NCLASS    55
#define D         56          // padded class dim (14 float4)
#define MAX_EDGES 800000
#define KMAX      512

typedef unsigned long long u64;

// ---------------- scratch (device globals) ---------------------------------
__device__ __align__(16) float g_bufA[MAX_NODES * D];
__device__ __align__(16) float g_bufB[MAX_NODES * D];
__device__ __align__(16) float g_inv_out[MAX_NODES];
__device__ __align__(16) float g_inv_in[MAX_NODES];
__device__ __align__(16) float g_s1[MAX_NODES];
__device__ __align__(16) int   g_off[MAX_NODES + 16];
__device__ __align__(16) int   g_cur[MAX_NODES];
__device__ __align__(16) int   g_csr[MAX_EDGES];
__device__ __align__(16) u64   g_state[64];               // decoupled-lookback states
__device__            int      g_wfdone;                  // Wfin-done counter
__device__ __align__(16) float g_T1[LAT * D];             // W2 @ Wc (padded)
__device__ __align__(16) float g_Wfin[LAT * D];           // W1 @ T1 (padded)
__device__ __align__(16) float g_Wall[KMAX * D];          // W_ext @ Wfin
__device__ __align__(16) float g_bfold[64];               // b_ext @ Wfin
__device__ __align__(16) float g_v1[64];                  // b1 @ T1
__device__ __align__(16) float g_c0[64];                  // b2 @ Wc + bc

// packed zero region: out_deg(f32) | deg_in(i32) | poolX[256*56] | poolD | cnt
#define ZR_OUTDEG 0
#define ZR_DEGIN  50000
#define ZR_POOLX  100000
#define ZR_POOLD  114336
#define ZR_CNT    114592
#define ZR_TOTAL  114848
__device__ __align__(16) float g_zregion[ZR_TOTAL];

// ---------------- f32x2 packed math helpers --------------------------------
__device__ __forceinline__ void ffma2(u64& d, u64 a, u64 b) {
    asm("fma.rn.f32x2 %0, %1, %2, %0;" : "+l"(d) : "l"(a), "l"(b));
}
__device__ __forceinline__ float2 unpack2(u64 v) {
    float2 f; asm("mov.b64 {%0, %1}, %2;" : "=f"(f.x), "=f"(f.y) : "l"(v)); return f;
}
__device__ __forceinline__ u64 swap2(u64 v) {
    float2 f = unpack2(v);
    u64 r; asm("mov.b64 %0, {%1, %2};" : "=l"(r) : "f"(f.y), "f"(f.x));
    return r;
}

// ---------------- cp.async helpers -----------------------------------------
__device__ __forceinline__ void cp_async16(uint32_t saddr, const void* gptr) {
    asm volatile("cp.async.ca.shared.global [%0], [%1], 16;"
                 :: "r"(saddr), "l"(gptr));
}
__device__ __forceinline__ void cp_commit() {
    asm volatile("cp.async.commit_group;");
}
__device__ __forceinline__ void cp_wait_all() {
    asm volatile("cp.async.wait_group 0;");
}

// ---------------- L1: prep (zero packed scratch + sync state) ---------------
__global__ void prep_kernel() {
    int i = blockIdx.x * blockDim.x + threadIdx.x;
    int stride = gridDim.x * blockDim.x;
    float4* z = (float4*)g_zregion;
    float4 zv = make_float4(0.f, 0.f, 0.f, 0.f);
    for (int t = i; t < ZR_TOTAL / 4; t += stride) z[t] = zv;
    if (i < 64) g_state[i] = 0ull;
    if (i == 64) g_wfdone = 0;
}

// ---------------- L2: degree histograms || T1 = W2 @ Wc ---------------------
#define WT_BLK 22   // ceil(100*56/256)
__global__ void fuse_deg_wT_kernel(const int* __restrict__ src,
                                   const int* __restrict__ dst, int E,
                                   const float* __restrict__ W2,
                                   const float* __restrict__ Wc) {
    if (blockIdx.x < WT_BLK) {
        int idx = blockIdx.x * 256 + threadIdx.x;
        if (idx < LAT * D) {
            int i = idx / D, j = idx - i * D;
            float a0 = 0.f, a1 = 0.f, a2 = 0.f, a3 = 0.f;
            if (j < NCLASS) {
                const float* w2r = W2 + i * H2;
#pragma unroll
                for (int k = 0; k < H2; k += 4) {
                    a0 += w2r[k]     * Wc[k * NCLASS + j];
                    a1 += w2r[k + 1] * Wc[(k + 1) * NCLASS + j];
                    a2 += w2r[k + 2] * Wc[(k + 2) * NCLASS + j];
                    a3 += w2r[k + 3] * Wc[(k + 3) * NCLASS + j];
                }
            }
            g_T1[idx] = (a0 + a1) + (a2 + a3);
        }
    } else {
        int i = (blockIdx.x - WT_BLK) * 256 + threadIdx.x;
        if (i < E) {
            float* out_deg = g_zregion + ZR_OUTDEG;
            int*   deg_in  = (int*)(g_zregion + ZR_DEGIN);
            atomicAdd(&out_deg[src[i]], 1.0f);
            atomicAdd(&deg_in[dst[i]], 1);
        }
    }
}

// ---------------- L3: single-pass scan || Wfin || Wall || biases ------------
#define WF_BLK 6
#define WA_BLK 14   // ceil(256*56/1024)
#define SCAN_BASE (WF_BLK + WA_BLK + 1)
__global__ void __launch_bounds__(1024) fuse_scan_fold_kernel(
        const int* __restrict__ gid, int n, int nb,
        const float* __restrict__ W1,
        const float* __restrict__ W_ext, int RAW,
        const float* __restrict__ b1,
        const float* __restrict__ b2,
        const float* __restrict__ Wc,
        const float* __restrict__ bc,
        const float* __restrict__ b_ext) {
    int tid = threadIdx.x;
    int b = blockIdx.x;

    if (b < WF_BLK) {
        int idx = b * 1024 + tid;
        if (idx < LAT * D) {
            int i = idx / D, j = idx - i * D;
            const float* w1r = W1 + i * LAT;
            float a0 = 0.f, a1 = 0.f, a2 = 0.f, a3 = 0.f;
#pragma unroll
            for (int k = 0; k < LAT; k += 4) {
                a0 += w1r[k]     * g_T1[k * D + j];
                a1 += w1r[k + 1] * g_T1[(k + 1) * D + j];
                a2 += w1r[k + 2] * g_T1[(k + 2) * D + j];
                a3 += w1r[k + 3] * g_T1[(k + 3) * D + j];
            }
            g_Wfin[idx] = (a0 + a1) + (a2 + a3);
        }
        __threadfence();
        __syncthreads();
        if (tid == 0) atomicAdd(&g_wfdone, 1);
        return;
    }
    if (b < WF_BLK + WA_BLK + 1) {
        if (tid == 0) {
            while (atomicAdd(&g_wfdone, 0) < WF_BLK) { }
        }
        __syncthreads();
        if (b < WF_BLK + WA_BLK) {
            __shared__ float sWf[LAT * D];
            for (int t = tid; t < LAT * D; t += 1024) sWf[t] = g_Wfin[t];
            __syncthreads();
            int idx = (b - WF_BLK) * 1024 + tid;
            if (idx < RAW * D) {
                int i = idx / D, c = idx - i * D;
                const float* wer = W_ext + i * LAT;
                float a0 = 0.f, a1 = 0.f, a2 = 0.f, a3 = 0.f;
#pragma unroll
                for (int k = 0; k < LAT; k += 4) {
                    a0 += wer[k]     * sWf[k * D + c];
                    a1 += wer[k + 1] * sWf[(k + 1) * D + c];
                    a2 += wer[k + 2] * sWf[(k + 2) * D + c];
                    a3 += wer[k + 3] * sWf[(k + 3) * D + c];
                }
                g_Wall[idx] = (a0 + a1) + (a2 + a3);
            }
        } else {
            int j = tid;
            if (j < D) {
                float v0 = 0.f, v1a = 0.f, f0 = 0.f, f1 = 0.f;
#pragma unroll
                for (int k = 0; k < LAT; k += 2) {
                    v0  += b1[k]        * g_T1[k * D + j];
                    v1a += b1[k + 1]    * g_T1[(k + 1) * D + j];
                    f0  += b_ext[k]     * g_Wfin[k * D + j];
                    f1  += b_ext[k + 1] * g_Wfin[(k + 1) * D + j];
                }
                g_v1[j] = v0 + v1a;
                g_bfold[j] = f0 + f1;
                if (j < NCLASS) {
                    float c0a = 0.f, c1 = 0.f, c2 = 0.f, c3 = 0.f;
#pragma unroll
                    for (int k = 0; k < H2; k += 4) {
                        c0a += b2[k]     * Wc[k * NCLASS + j];
                        c1  += b2[k + 1] * Wc[(k + 1) * NCLASS + j];
                        c2  += b2[k + 2] * Wc[(k + 2) * NCLASS + j];
                        c3  += b2[k + 3] * Wc[(k + 3) * NCLASS + j];
                    }
                    g_c0[j] = (c0a + c1) + (c2 + c3) + bc[j];
                }
            }
        }
        return;
    }

    // ---- scan blocks: decoupled lookback over deg_in ----
    __shared__ int wsum[32];
    __shared__ int s_prefix;
    const float* out_deg = g_zregion + ZR_OUTDEG;
    const int*   deg_in  = (const int*)(g_zregion + ZR_DEGIN);
    float* cnt = g_zregion + ZR_CNT;
    int bb = b - SCAN_BASE;
    int lane = tid & 31, warp = tid >> 5;
    int i = bb * 1024 + tid;
    int v = 0;
    if (i < n) {
        v = deg_in[i];
        float ii = rsqrtf(fmaxf((float)v, 1.0f));
        float io = rsqrtf(fmaxf(out_deg[i], 1.0f));
        g_inv_in[i]  = ii;
        g_inv_out[i] = io;
        g_s1[i]      = ii * io;
        atomicAdd(&cnt[gid[i]], 1.0f);
    }
    int s = v;
#pragma unroll
    for (int d = 1; d < 32; d <<= 1) {
        int t = __shfl_up_sync(0xffffffffu, s, d);
        if (lane >= d) s += t;
    }
    if (lane == 31) wsum[warp] = s;
    __syncthreads();
    if (warp == 0) {
        int ws = wsum[lane];
#pragma unroll
        for (int d = 1; d < 32; d <<= 1) {
            int t = __shfl_up_sync(0xffffffffu, ws, d);
            if (lane >= d) ws += t;
        }
        wsum[lane] = ws;
    }
    __syncthreads();
    int wpre = (warp > 0) ? wsum[warp - 1] : 0;
    int total = wsum[31];
    if (tid == 0) {
        int run = 0;
        if (bb == 0) {
            atomicExch(&g_state[0], (2ull << 32) | (unsigned)total);
        } else {
            atomicExch(&g_state[bb], (1ull << 32) | (unsigned)total);
            int j = bb - 1;
            while (j >= 0) {
                u64 st;
                do { st = atomicAdd(&g_state[j], 0ull); } while ((st >> 32) == 0);
                run += (int)(unsigned)st;
                if ((st >> 32) == 2ull) break;
                j--;
            }
            atomicExch(&g_state[bb], (2ull << 32) | (unsigned)(run + total));
        }
        s_prefix = run;
    }
    __syncthreads();
    int excl = s - v + wpre + s_prefix;
    if (i < n) { g_off[i] = excl; g_cur[i] = excl; }
    if (bb == nb - 1 && tid == 0) g_off[n] = s_prefix + total;
}

// ---------------- L4: persistent scatter blocks || GEMM0 --------------------
// Blocks [0, ns): grid-stride CSR scatter (co-resident with gemm wave,
// 4-way unrolled for atomic-latency MLP). Blocks [ns, ns+gb): gemm.
#define TM 128
#define KC 32
#define SA 132
#define SW 60
#define ABUF (KC * SA)
#define WBUF (KC * SW)
#define GSMEM ((2 * ABUF + 2 * WBUF) * 4)
__global__ void __launch_bounds__(256, 3) fuse_gemm_scatter_kernel(
        const float* __restrict__ A,
        const float* __restrict__ Wn,
        const float* __restrict__ bias,
        const float* __restrict__ sout,
        float* __restrict__ C, int M, int K, int ns,
        const int* __restrict__ src, const int* __restrict__ dst, int E) {
    if (blockIdx.x < ns) {
        int t = blockIdx.x * 256 + threadIdx.x;
        int stride = ns * 256;
        int e = t;
        for (; e + 3 * stride < E; e += 4 * stride) {
            int d0 = dst[e], d1 = dst[e + stride];
            int d2 = dst[e + 2 * stride], d3 = dst[e + 3 * stride];
            int s0 = src[e], s1 = src[e + stride];
            int s2 = src[e + 2 * stride], s3 = src[e + 3 * stride];
            int p0 = atomicAdd(&g_cur[d0], 1);
            int p1 = atomicAdd(&g_cur[d1], 1);
            int p2 = atomicAdd(&g_cur[d2], 1);
            int p3 = atomicAdd(&g_cur[d3], 1);
            g_csr[p0] = s0; g_csr[p1] = s1; g_csr[p2] = s2; g_csr[p3] = s3;
        }
        for (; e < E; e += stride) {
            int p = atomicAdd(&g_cur[dst[e]], 1);
            g_csr[p] = src[e];
        }
        return;
    }
    extern __shared__ float sm[];
    float* AsB = sm;
    float* WsB = sm + 2 * ABUF;
    uint32_t wbase = (uint32_t)__cvta_generic_to_shared(WsB);

    int tid = threadIdx.x;
    int m0 = (blockIdx.x - ns) * TM;
    bool worker = tid < 224;
    int ty = tid / 14;
    int tx = tid - ty * 14;
    int r0 = ty * 8;
    int c0 = tx * 4;

    u64 accd[4][2], accx[4][2];
#pragma unroll
    for (int p = 0; p < 4; p++) {
        accd[p][0] = accd[p][1] = 0ull;
        accx[p][0] = accx[p][1] = 0ull;
    }

    float4 aQ[4];
    int nk = (K + KC - 1) / KC;

    auto loadW = [&](int k0, int buf) {
#pragma unroll
        for (int s = 0; s < 2; s++) {
            int idx = tid + s * 256;
            if (idx < KC * 14) {
                int kk = idx / 14, c4 = idx - kk * 14;
                int gk = k0 + kk;
                uint32_t dstp = wbase + (buf * WBUF + kk * SW + c4 * 4) * 4;
                if (gk < K) {
                    cp_async16(dstp, &Wn[(size_t)gk * D + c4 * 4]);
                } else {
                    float* d = WsB + buf * WBUF + kk * SW + c4 * 4;
                    d[0] = d[1] = d[2] = d[3] = 0.f;
                }
            }
        }
    };
    auto loadA = [&](int k0) {
#pragma unroll
        for (int s = 0; s < 4; s++) {
            int idx = tid + s * 256;
            int row = idx >> 3, q = idx & 7;
            int gr = m0 + row; if (gr >= M) gr = M - 1;
            int gk = k0 + q * 4;
            if (gk + 3 < K) {
                aQ[s] = *(const float4*)&A[(size_t)gr * K + gk];
            } else {
                aQ[s].x = (gk     < K) ? A[(size_t)gr * K + gk]     : 0.f;
                aQ[s].y = (gk + 1 < K) ? A[(size_t)gr * K + gk + 1] : 0.f;
                aQ[s].z = (gk + 2 < K) ? A[(size_t)gr * K + gk + 2] : 0.f;
                aQ[s].w = (gk + 3 < K) ? A[(size_t)gr * K + gk + 3] : 0.f;
            }
        }
    };
    auto storeA = [&](int buf) {
        float* Ab = AsB + buf * ABUF;
#pragma unroll
        for (int s = 0; s < 4; s++) {
            int idx = tid + s * 256;
            int row = idx >> 3, q = idx & 7;
            float* dstp = Ab + (q * 4) * SA + row;
            dstp[0] = aQ[s].x; dstp[SA] = aQ[s].y; dstp[2 * SA] = aQ[s].z; dstp[3 * SA] = aQ[s].w;
        }
    };

    loadW(0, 0);
    cp_commit();
    loadA(0);
    storeA(0);
    cp_wait_all();
    __syncthreads();

    for (int ch = 0; ch < nk; ch++) {
        int buf = ch & 1;
        if (ch + 1 < nk) {
            loadA((ch + 1) * KC);
            loadW((ch + 1) * KC, buf ^ 1);
            cp_commit();
        }
        if (worker) {
            const float* Ab = AsB + buf * ABUF;
            const float* Wb = WsB + buf * WBUF;
#pragma unroll 4
            for (int k = 0; k < KC; k++) {
                ulonglong2 a01 = *(const ulonglong2*)(Ab + k * SA + r0);
                ulonglong2 a23 = *(const ulonglong2*)(Ab + k * SA + r0 + 4);
                ulonglong2 w   = *(const ulonglong2*)(Wb + k * SW + c0);
                u64 wxs = swap2(w.x);
                u64 wys = swap2(w.y);
                ffma2(accd[0][0], a01.x, w.x);  ffma2(accx[0][0], a01.x, wxs);
                ffma2(accd[0][1], a01.x, w.y);  ffma2(accx[0][1], a01.x, wys);
                ffma2(accd[1][0], a01.y, w.x);  ffma2(accx[1][0], a01.y, wxs);
                ffma2(accd[1][1], a01.y, w.y);  ffma2(accx[1][1], a01.y, wys);
                ffma2(accd[2][0], a23.x, w.x);  ffma2(accx[2][0], a23.x, wxs);
                ffma2(accd[2][1], a23.x, w.y);  ffma2(accx[2][1], a23.x, wys);
                ffma2(accd[3][0], a23.y, w.x);  ffma2(accx[3][0], a23.y, wxs);
                ffma2(accd[3][1], a23.y, w.y);  ffma2(accx[3][1], a23.y, wys);
            }
        }
        if (ch + 1 < nk) {
            storeA(buf ^ 1);
            cp_wait_all();
            __syncthreads();
        }
    }

    if (worker) {
        float4 bv = *(const float4*)&bias[c0];
#pragma unroll
        for (int p = 0; p < 4; p++) {
            float2 d0 = unpack2(accd[p][0]);
            float2 x0 = unpack2(accx[p][0]);
            float2 d1 = unpack2(accd[p][1]);
            float2 x1 = unpack2(accx[p][1]);
            int row = m0 + r0 + 2 * p;
            if (row < M) {
                float so = sout[row];
                float4 v = make_float4((d0.x + bv.x) * so, (x0.x + bv.y) * so,
                                       (d1.x + bv.z) * so, (x1.x + bv.w) * so);
                *(float4*)&C[(size_t)row * D + c0] = v;
            }
            if (row + 1 < M) {
                float so = sout[row + 1];
                float4 v = make_float4((x0.y + bv.x) * so, (d0.y + bv.y) * so,
                                       (x1.y + bv.z) * so, (d1.y + bv.w) * so);
                *(float4*)&C[(size_t)(row + 1) * D + c0] = v;
            }
        }
    }
}

// ---------------- L5/L6: CSR propagation (unroll 8, half-warp per node) -----
template <bool POOL>
__global__ void prop_csr_kernel(const float4* __restrict__ xs,
                                float4* __restrict__ agg,
                                const float* __restrict__ scale,
                                const int* __restrict__ gid, int n) {
    int node = (blockIdx.x * blockDim.x + threadIdx.x) >> 4;
    int l = threadIdx.x & 15;
    if (node >= n) return;
    int b = g_off[node], e = g_off[node + 1];
    bool act = l < 14;
    bool dt  = (!POOL) && (l == 14);
    float4 a0 = make_float4(0.f, 0.f, 0.f, 0.f);
    float4 a1 = a0, a2 = a0, a3 = a0;
    float sd = 0.f;
    unsigned base = (unsigned)l;
    int k = b;
    for (; k + 8 <= e; k += 8) {
        int s0 = g_csr[k],     s1 = g_csr[k + 1], s2 = g_csr[k + 2], s3 = g_csr[k + 3];
        int s4 = g_csr[k + 4], s5 = g_csr[k + 5], s6 = g_csr[k + 6], s7 = g_csr[k + 7];
        if (act) {
            float4 v0 = xs[(unsigned)s0 * 14u + base];
            float4 v1 = xs[(unsigned)s1 * 14u + base];
            float4 v2 = xs[(unsigned)s2 * 14u + base];
            float4 v3 = xs[(unsigned)s3 * 14u + base];
            float4 v4 = xs[(unsigned)s4 * 14u + base];
            float4 v5 = xs[(unsigned)s5 * 14u + base];
            float4 v6 = xs[(unsigned)s6 * 14u + base];
            float4 v7 = xs[(unsigned)s7 * 14u + base];
            a0.x += v0.x + v4.x; a0.y += v0.y + v4.y; a0.z += v0.z + v4.z; a0.w += v0.w + v4.w;
            a1.x += v1.x + v5.x; a1.y += v1.y + v5.y; a1.z += v1.z + v5.z; a1.w += v1.w + v5.w;
            a2.x += v2.x + v6.x; a2.y += v2.y + v6.y; a2.z += v2.z + v6.z; a2.w += v2.w + v6.w;
            a3.x += v3.x + v7.x; a3.y += v3.y + v7.y; a3.z += v3.z + v7.z; a3.w += v3.w + v7.w;
        } else if (dt) {
            sd += g_inv_out[s0] + g_inv_out[s1] + g_inv_out[s2] + g_inv_out[s3]
                + g_inv_out[s4] + g_inv_out[s5] + g_inv_out[s6] + g_inv_out[s7];
        }
    }
    for (; k + 2 <= e; k += 2) {
        int s0 = g_csr[k], s1 = g_csr[k + 1];
        if (act) {
            float4 v0 = xs[(unsigned)s0 * 14u + base];
            float4 v1 = xs[(unsigned)s1 * 14u + base];
            a0.x += v0.x; a0.y += v0.y; a0.z += v0.z; a0.w += v0.w;
            a1.x += v1.x; a1.y += v1.y; a1.z += v1.z; a1.w += v1.w;
        } else if (dt) {
            sd += g_inv_out[s0] + g_inv_out[s1];
        }
    }
    if (k < e) {
        int s0 = g_csr[k];
        if (act) {
            float4 v0 = xs[(unsigned)s0 * 14u + base];
            a0.x += v0.x; a0.y += v0.y; a0.z += v0.z; a0.w += v0.w;
        } else if (dt) {
            sd += g_inv_out[s0];
        }
    }
    if (act) {
        float sc = scale[node];
        float x = (a0.x + a1.x + a2.x + a3.x) * sc;
        float y = (a0.y + a1.y + a2.y + a3.y) * sc;
        float z = (a0.z + a1.z + a2.z + a3.z) * sc;
        float w = (a0.w + a1.w + a2.w + a3.w) * sc;
        if (!POOL) {
            agg[(unsigned)node * 14u + base] = make_float4(x, y, z, w);
        } else {
            float* poolX = g_zregion + ZR_POOLX;
            float* p = poolX + (unsigned)gid[node] * D + base * 4u;
            asm volatile("red.global.add.v4.f32 [%0], {%1,%2,%3,%4};"
                         :: "l"(p), "f"(x), "f"(y), "f"(z), "f"(w)
                         : "memory");
        }
    } else if (dt) {
        float* poolD = g_zregion + ZR_POOLD;
        atomicAdd(&poolD[gid[node]], sd * g_inv_in[node]);
    }
}

// ---------------- L7: final --------------------------------------------------
__global__ void final_kernel(float* __restrict__ out) {
    const float* poolX = g_zregion + ZR_POOLX;
    const float* poolD = g_zregion + ZR_POOLD;
    const float* cnt   = g_zregion + ZR_CNT;
    int g = blockIdx.x, tid = threadIdx.x;
    if (tid < NCLASS) {
        float invc = 1.0f / fmaxf(cnt[g], 1.0f);
        out[g * NCLASS + tid] = poolX[g * D + tid] * invc
                              + poolD[g] * invc * g_v1[tid]
                              + g_c0[tid];
    }
}

// ---------------- launch ---------------------------------------------------
extern "C" void kernel_launch(void* const* d_in, const int* in_sizes, int n_in,
                              void* d_out, int out_size) {
    const float* fsnet = (const float*)d_in[0];
    const int*   src   = (const int*)d_in[1];
    const int*   dst   = (const int*)d_in[2];
    const int*   gid   = (const int*)d_in[3];
    const float* W_ext = (const float*)d_in[4];
    const float* b_ext = (const float*)d_in[5];
    const float* W1    = (const float*)d_in[6];
    const float* b1    = (const float*)d_in[7];
    const float* W2    = (const float*)d_in[8];
    const float* b2    = (const float*)d_in[9];
    const float* Wc    = (const float*)d_in[10];
    const float* bc    = (const float*)d_in[11];
    float* out = (float*)d_out;

    int n   = in_sizes[3];
    int E   = in_sizes[1];
    int RAW = in_sizes[4] / LAT;

    float *bufA, *bufB, *inv_out, *inv_in, *s1, *wall, *bfold;
    cudaGetSymbolAddress((void**)&bufA,    g_bufA);
    cudaGetSymbolAddress((void**)&bufB,    g_bufB);
    cudaGetSymbolAddress((void**)&inv_out, g_inv_out);
    cudaGetSymbolAddress((void**)&inv_in,  g_inv_in);
    cudaGetSymbolAddress((void**)&s1,      g_s1);
    cudaGetSymbolAddress((void**)&wall,    g_Wall);
    cudaGetSymbolAddress((void**)&bfold,   g_bfold);

    cudaFuncSetAttribute(fuse_gemm_scatter_kernel,
                         cudaFuncAttributeMaxDynamicSharedMemorySize, GSMEM);

    int nb = (n + 1023) / 1024;          // scan blocks
    int eb = (E + 255) / 256;            // edge blocks (degree launch)
    int gb = (n + TM - 1) / TM;          // gemm blocks
    int ns = 148 * 3 - gb;               // co-resident scatter blocks
    if (ns < 16) ns = 16;
    if (ns > 148) ns = 148;

    // L1: zero packed scratch + lookback state
    prep_kernel<<<148, 256>>>();
    // L2: degree histograms || T1 = W2@Wc
    fuse_deg_wT_kernel<<<WT_BLK + eb, 256>>>(src, dst, E, W2, Wc);
    // L3: single-pass scan || Wfin || Wall || biases (flag-ordered)
    fuse_scan_fold_kernel<<<SCAN_BASE + nb, 1024>>>(
        gid, n, nb, W1, W_ext, RAW, b1, b2, Wc, bc, b_ext);
    // L4: persistent scatter blocks || GEMM0 (all co-resident in wave 1)
    fuse_gemm_scatter_kernel<<<ns + gb, 256, GSMEM>>>(
        fsnet, wall, bfold, inv_out, bufA, n, RAW, ns, src, dst, E);
    // L5: prop1 (+ fused dtilde): bufB = P(z0) * s1
    int pblocks = (n * 16 + 255) / 256;
    prop_csr_kernel<false><<<pblocks, 256>>>((const float4*)bufA, (float4*)bufB, s1, gid, n);
    // L6: prop2 fused with graph pooling
    prop_csr_kernel<true><<<pblocks, 256>>>((const float4*)bufB, nullptr, inv_in, gid, n);
    // L7: out = poolX/cnt + (poolD/cnt)*v1 + c0
    final_kernel<<<NGRAPH, 64>>>(out);
}

// round 17
// speedup vs baseline: 1.0893x; 1.0132x over previous
#include <cuda_runtime.h>
#include <cstdint>

#define MAX_NODES 50000
#define LAT       100
#define NGRAPH    256
#define H2        200
#define NCLASS    55
#define D         56          // padded class dim (14 float4)
#define MAX_EDGES 800000
#define KMAX      512

typedef unsigned long long u64;

// ---------------- scratch (device globals) ---------------------------------
__device__ __align__(16) float g_bufA[MAX_NODES * D];
__device__ __align__(16) float g_bufB[MAX_NODES * D];
__device__ __align__(16) float g_inv_out[MAX_NODES];
__device__ __align__(16) float g_inv_in[MAX_NODES];
__device__ __align__(16) float g_s1[MAX_NODES];
__device__ __align__(16) int   g_off[MAX_NODES + 16];
__device__ __align__(16) int   g_cur[MAX_NODES];
__device__ __align__(16) int   g_csr[MAX_EDGES];
__device__ __align__(16) u64   g_state[64];               // decoupled-lookback states
__device__            int      g_wfdone;                  // Wfin-done counter
__device__ __align__(16) float g_T1[LAT * D];             // W2 @ Wc (padded)
__device__ __align__(16) float g_Wfin[LAT * D];           // W1 @ T1 (padded)
__device__ __align__(16) float g_Wall[KMAX * D];          // W_ext @ Wfin
__device__ __align__(16) float g_bfold[64];               // b_ext @ Wfin
__device__ __align__(16) float g_v1[64];                  // b1 @ T1
__device__ __align__(16) float g_c0[64];                  // b2 @ Wc + bc

// packed zero region: out_deg(f32) | deg_in(i32) | poolX[256*56] | poolD | cnt
#define ZR_OUTDEG 0
#define ZR_DEGIN  50000
#define ZR_POOLX  100000
#define ZR_POOLD  114336
#define ZR_CNT    114592
#define ZR_TOTAL  114848
__device__ __align__(16) float g_zregion[ZR_TOTAL];

// ---------------- f32x2 packed math helpers --------------------------------
__device__ __forceinline__ void ffma2(u64& d, u64 a, u64 b) {
    asm("fma.rn.f32x2 %0, %1, %2, %0;" : "+l"(d) : "l"(a), "l"(b));
}
__device__ __forceinline__ float2 unpack2(u64 v) {
    float2 f; asm("mov.b64 {%0, %1}, %2;" : "=f"(f.x), "=f"(f.y) : "l"(v)); return f;
}
__device__ __forceinline__ u64 swap2(u64 v) {
    float2 f = unpack2(v);
    u64 r; asm("mov.b64 %0, {%1, %2};" : "=l"(r) : "f"(f.y), "f"(f.x));
    return r;
}

// ---------------- cp.async helpers -----------------------------------------
__device__ __forceinline__ void cp_async16(uint32_t saddr, const void* gptr) {
    asm volatile("cp.async.ca.shared.global [%0], [%1], 16;"
                 :: "r"(saddr), "l"(gptr));
}
__device__ __forceinline__ void cp_commit() {
    asm volatile("cp.async.commit_group;");
}
__device__ __forceinline__ void cp_wait_all() {
    asm volatile("cp.async.wait_group 0;");
}

// ---------------- L1: prep (zero packed scratch + sync state) ---------------
__global__ void prep_kernel() {
    int i = blockIdx.x * blockDim.x + threadIdx.x;
    int stride = gridDim.x * blockDim.x;
    float4* z = (float4*)g_zregion;
    float4 zv = make_float4(0.f, 0.f, 0.f, 0.f);
    for (int t = i; t < ZR_TOTAL / 4; t += stride) z[t] = zv;
    if (i < 64) g_state[i] = 0ull;
    if (i == 64) g_wfdone = 0;
}

// ---------------- L2: degree histograms || T1 = W2 @ Wc ---------------------
#define WT_BLK 22   // ceil(100*56/256)
__global__ void fuse_deg_wT_kernel(const int* __restrict__ src,
                                   const int* __restrict__ dst, int E,
                                   const float* __restrict__ W2,
                                   const float* __restrict__ Wc) {
    if (blockIdx.x < WT_BLK) {
        int idx = blockIdx.x * 256 + threadIdx.x;
        if (idx < LAT * D) {
            int i = idx / D, j = idx - i * D;
            float a0 = 0.f, a1 = 0.f, a2 = 0.f, a3 = 0.f;
            if (j < NCLASS) {
                const float* w2r = W2 + i * H2;
#pragma unroll
                for (int k = 0; k < H2; k += 4) {
                    a0 += w2r[k]     * Wc[k * NCLASS + j];
                    a1 += w2r[k + 1] * Wc[(k + 1) * NCLASS + j];
                    a2 += w2r[k + 2] * Wc[(k + 2) * NCLASS + j];
                    a3 += w2r[k + 3] * Wc[(k + 3) * NCLASS + j];
                }
            }
            g_T1[idx] = (a0 + a1) + (a2 + a3);
        }
    } else {
        int i = (blockIdx.x - WT_BLK) * 256 + threadIdx.x;
        if (i < E) {
            float* out_deg = g_zregion + ZR_OUTDEG;
            int*   deg_in  = (int*)(g_zregion + ZR_DEGIN);
            atomicAdd(&out_deg[src[i]], 1.0f);
            atomicAdd(&deg_in[dst[i]], 1);
        }
    }
}

// ---------------- L3: single-pass scan || Wfin || Wall || biases ------------
#define WF_BLK 6
#define WA_BLK 14   // ceil(256*56/1024)
#define SCAN_BASE (WF_BLK + WA_BLK + 1)
__global__ void __launch_bounds__(1024) fuse_scan_fold_kernel(
        const int* __restrict__ gid, int n, int nb,
        const float* __restrict__ W1,
        const float* __restrict__ W_ext, int RAW,
        const float* __restrict__ b1,
        const float* __restrict__ b2,
        const float* __restrict__ Wc,
        const float* __restrict__ bc,
        const float* __restrict__ b_ext) {
    int tid = threadIdx.x;
    int b = blockIdx.x;

    if (b < WF_BLK) {
        int idx = b * 1024 + tid;
        if (idx < LAT * D) {
            int i = idx / D, j = idx - i * D;
            const float* w1r = W1 + i * LAT;
            float a0 = 0.f, a1 = 0.f, a2 = 0.f, a3 = 0.f;
#pragma unroll
            for (int k = 0; k < LAT; k += 4) {
                a0 += w1r[k]     * g_T1[k * D + j];
                a1 += w1r[k + 1] * g_T1[(k + 1) * D + j];
                a2 += w1r[k + 2] * g_T1[(k + 2) * D + j];
                a3 += w1r[k + 3] * g_T1[(k + 3) * D + j];
            }
            g_Wfin[idx] = (a0 + a1) + (a2 + a3);
        }
        __threadfence();
        __syncthreads();
        if (tid == 0) atomicAdd(&g_wfdone, 1);
        return;
    }
    if (b < WF_BLK + WA_BLK + 1) {
        if (tid == 0) {
            while (atomicAdd(&g_wfdone, 0) < WF_BLK) { }
        }
        __syncthreads();
        if (b < WF_BLK + WA_BLK) {
            __shared__ float sWf[LAT * D];
            for (int t = tid; t < LAT * D; t += 1024) sWf[t] = g_Wfin[t];
            __syncthreads();
            int idx = (b - WF_BLK) * 1024 + tid;
            if (idx < RAW * D) {
                int i = idx / D, c = idx - i * D;
                const float* wer = W_ext + i * LAT;
                float a0 = 0.f, a1 = 0.f, a2 = 0.f, a3 = 0.f;
#pragma unroll
                for (int k = 0; k < LAT; k += 4) {
                    a0 += wer[k]     * sWf[k * D + c];
                    a1 += wer[k + 1] * sWf[(k + 1) * D + c];
                    a2 += wer[k + 2] * sWf[(k + 2) * D + c];
                    a3 += wer[k + 3] * sWf[(k + 3) * D + c];
                }
                g_Wall[idx] = (a0 + a1) + (a2 + a3);
            }
        } else {
            int j = tid;
            if (j < D) {
                float v0 = 0.f, v1a = 0.f, f0 = 0.f, f1 = 0.f;
#pragma unroll
                for (int k = 0; k < LAT; k += 2) {
                    v0  += b1[k]        * g_T1[k * D + j];
                    v1a += b1[k + 1]    * g_T1[(k + 1) * D + j];
                    f0  += b_ext[k]     * g_Wfin[k * D + j];
                    f1  += b_ext[k + 1] * g_Wfin[(k + 1) * D + j];
                }
                g_v1[j] = v0 + v1a;
                g_bfold[j] = f0 + f1;
                if (j < NCLASS) {
                    float c0a = 0.f, c1 = 0.f, c2 = 0.f, c3 = 0.f;
#pragma unroll
                    for (int k = 0; k < H2; k += 4) {
                        c0a += b2[k]     * Wc[k * NCLASS + j];
                        c1  += b2[k + 1] * Wc[(k + 1) * NCLASS + j];
                        c2  += b2[k + 2] * Wc[(k + 2) * NCLASS + j];
                        c3  += b2[k + 3] * Wc[(k + 3) * NCLASS + j];
                    }
                    g_c0[j] = (c0a + c1) + (c2 + c3) + bc[j];
                }
            }
        }
        return;
    }

    // ---- scan blocks: decoupled lookback over deg_in ----
    __shared__ int wsum[32];
    __shared__ int s_prefix;
    const float* out_deg = g_zregion + ZR_OUTDEG;
    const int*   deg_in  = (const int*)(g_zregion + ZR_DEGIN);
    float* cnt = g_zregion + ZR_CNT;
    int bb = b - SCAN_BASE;
    int lane = tid & 31, warp = tid >> 5;
    int i = bb * 1024 + tid;
    int v = 0;
    if (i < n) {
        v = deg_in[i];
        float ii = rsqrtf(fmaxf((float)v, 1.0f));
        float io = rsqrtf(fmaxf(out_deg[i], 1.0f));
        g_inv_in[i]  = ii;
        g_inv_out[i] = io;
        g_s1[i]      = ii * io;
        atomicAdd(&cnt[gid[i]], 1.0f);
    }
    int s = v;
#pragma unroll
    for (int d = 1; d < 32; d <<= 1) {
        int t = __shfl_up_sync(0xffffffffu, s, d);
        if (lane >= d) s += t;
    }
    if (lane == 31) wsum[warp] = s;
    __syncthreads();
    if (warp == 0) {
        int ws = wsum[lane];
#pragma unroll
        for (int d = 1; d < 32; d <<= 1) {
            int t = __shfl_up_sync(0xffffffffu, ws, d);
            if (lane >= d) ws += t;
        }
        wsum[lane] = ws;
    }
    __syncthreads();
    int wpre = (warp > 0) ? wsum[warp - 1] : 0;
    int total = wsum[31];
    if (tid == 0) {
        int run = 0;
        if (bb == 0) {
            atomicExch(&g_state[0], (2ull << 32) | (unsigned)total);
        } else {
            atomicExch(&g_state[bb], (1ull << 32) | (unsigned)total);
            int j = bb - 1;
            while (j >= 0) {
                u64 st;
                do { st = atomicAdd(&g_state[j], 0ull); } while ((st >> 32) == 0);
                run += (int)(unsigned)st;
                if ((st >> 32) == 2ull) break;
                j--;
            }
            atomicExch(&g_state[bb], (2ull << 32) | (unsigned)(run + total));
        }
        s_prefix = run;
    }
    __syncthreads();
    int excl = s - v + wpre + s_prefix;
    if (i < n) { g_off[i] = excl; g_cur[i] = excl; }
    if (bb == nb - 1 && tid == 0) g_off[n] = s_prefix + total;
}

// ---------------- L4: persistent scatter blocks || GEMM0 --------------------
#define TM 128
#define KC 32
#define SA 132
#define SW 60
#define ABUF (KC * SA)
#define WBUF (KC * SW)
#define GSMEM ((2 * ABUF + 2 * WBUF) * 4)
__global__ void __launch_bounds__(256, 3) fuse_gemm_scatter_kernel(
        const float* __restrict__ A,
        const float* __restrict__ Wn,
        const float* __restrict__ bias,
        const float* __restrict__ sout,
        float* __restrict__ C, int M, int K, int ns,
        const int* __restrict__ src, const int* __restrict__ dst, int E) {
    if (blockIdx.x < ns) {
        int t = blockIdx.x * 256 + threadIdx.x;
        int stride = ns * 256;
        int e = t;
        for (; e + 3 * stride < E; e += 4 * stride) {
            int d0 = dst[e], d1 = dst[e + stride];
            int d2 = dst[e + 2 * stride], d3 = dst[e + 3 * stride];
            int s0 = src[e], s1 = src[e + stride];
            int s2 = src[e + 2 * stride], s3 = src[e + 3 * stride];
            int p0 = atomicAdd(&g_cur[d0], 1);
            int p1 = atomicAdd(&g_cur[d1], 1);
            int p2 = atomicAdd(&g_cur[d2], 1);
            int p3 = atomicAdd(&g_cur[d3], 1);
            g_csr[p0] = s0; g_csr[p1] = s1; g_csr[p2] = s2; g_csr[p3] = s3;
        }
        for (; e < E; e += stride) {
            int p = atomicAdd(&g_cur[dst[e]], 1);
            g_csr[p] = src[e];
        }
        return;
    }
    extern __shared__ float sm[];
    float* AsB = sm;
    float* WsB = sm + 2 * ABUF;
    uint32_t wbase = (uint32_t)__cvta_generic_to_shared(WsB);

    int tid = threadIdx.x;
    int m0 = (blockIdx.x - ns) * TM;
    bool worker = tid < 224;
    int ty = tid / 14;
    int tx = tid - ty * 14;
    int r0 = ty * 8;
    int c0 = tx * 4;

    u64 accd[4][2], accx[4][2];
#pragma unroll
    for (int p = 0; p < 4; p++) {
        accd[p][0] = accd[p][1] = 0ull;
        accx[p][0] = accx[p][1] = 0ull;
    }

    float4 aQ[4];
    int nk = (K + KC - 1) / KC;

    auto loadW = [&](int k0, int buf) {
#pragma unroll
        for (int s = 0; s < 2; s++) {
            int idx = tid + s * 256;
            if (idx < KC * 14) {
                int kk = idx / 14, c4 = idx - kk * 14;
                int gk = k0 + kk;
                uint32_t dstp = wbase + (buf * WBUF + kk * SW + c4 * 4) * 4;
                if (gk < K) {
                    cp_async16(dstp, &Wn[(size_t)gk * D + c4 * 4]);
                } else {
                    float* d = WsB + buf * WBUF + kk * SW + c4 * 4;
                    d[0] = d[1] = d[2] = d[3] = 0.f;
                }
            }
        }
    };
    auto loadA = [&](int k0) {
#pragma unroll
        for (int s = 0; s < 4; s++) {
            int idx = tid + s * 256;
            int row = idx >> 3, q = idx & 7;
            int gr = m0 + row; if (gr >= M) gr = M - 1;
            int gk = k0 + q * 4;
            if (gk + 3 < K) {
                aQ[s] = *(const float4*)&A[(size_t)gr * K + gk];
            } else {
                aQ[s].x = (gk     < K) ? A[(size_t)gr * K + gk]     : 0.f;
                aQ[s].y = (gk + 1 < K) ? A[(size_t)gr * K + gk + 1] : 0.f;
                aQ[s].z = (gk + 2 < K) ? A[(size_t)gr * K + gk + 2] : 0.f;
                aQ[s].w = (gk + 3 < K) ? A[(size_t)gr * K + gk + 3] : 0.f;
            }
        }
    };
    auto storeA = [&](int buf) {
        float* Ab = AsB + buf * ABUF;
#pragma unroll
        for (int s = 0; s < 4; s++) {
            int idx = tid + s * 256;
            int row = idx >> 3, q = idx & 7;
            float* dstp = Ab + (q * 4) * SA + row;
            dstp[0] = aQ[s].x; dstp[SA] = aQ[s].y; dstp[2 * SA] = aQ[s].z; dstp[3 * SA] = aQ[s].w;
        }
    };

    loadW(0, 0);
    cp_commit();
    loadA(0);
    storeA(0);
    cp_wait_all();
    __syncthreads();

    for (int ch = 0; ch < nk; ch++) {
        int buf = ch & 1;
        if (ch + 1 < nk) {
            loadA((ch + 1) * KC);
            loadW((ch + 1) * KC, buf ^ 1);
            cp_commit();
        }
        if (worker) {
            const float* Ab = AsB + buf * ABUF;
            const float* Wb = WsB + buf * WBUF;
#pragma unroll 4
            for (int k = 0; k < KC; k++) {
                ulonglong2 a01 = *(const ulonglong2*)(Ab + k * SA + r0);
                ulonglong2 a23 = *(const ulonglong2*)(Ab + k * SA + r0 + 4);
                ulonglong2 w   = *(const ulonglong2*)(Wb + k * SW + c0);
                u64 wxs = swap2(w.x);
                u64 wys = swap2(w.y);
                ffma2(accd[0][0], a01.x, w.x);  ffma2(accx[0][0], a01.x, wxs);
                ffma2(accd[0][1], a01.x, w.y);  ffma2(accx[0][1], a01.x, wys);
                ffma2(accd[1][0], a01.y, w.x);  ffma2(accx[1][0], a01.y, wxs);
                ffma2(accd[1][1], a01.y, w.y);  ffma2(accx[1][1], a01.y, wys);
                ffma2(accd[2][0], a23.x, w.x);  ffma2(accx[2][0], a23.x, wxs);
                ffma2(accd[2][1], a23.x, w.y);  ffma2(accx[2][1], a23.x, wys);
                ffma2(accd[3][0], a23.y, w.x);  ffma2(accx[3][0], a23.y, wxs);
                ffma2(accd[3][1], a23.y, w.y);  ffma2(accx[3][1], a23.y, wys);
            }
        }
        if (ch + 1 < nk) {
            storeA(buf ^ 1);
            cp_wait_all();
            __syncthreads();
        }
    }

    if (worker) {
        float4 bv = *(const float4*)&bias[c0];
#pragma unroll
        for (int p = 0; p < 4; p++) {
            float2 d0 = unpack2(accd[p][0]);
            float2 x0 = unpack2(accx[p][0]);
            float2 d1 = unpack2(accd[p][1]);
            float2 x1 = unpack2(accx[p][1]);
            int row = m0 + r0 + 2 * p;
            if (row < M) {
                float so = sout[row];
                float4 v = make_float4((d0.x + bv.x) * so, (x0.x + bv.y) * so,
                                       (d1.x + bv.z) * so, (x1.x + bv.w) * so);
                *(float4*)&C[(size_t)row * D + c0] = v;
            }
            if (row + 1 < M) {
                float so = sout[row + 1];
                float4 v = make_float4((x0.y + bv.x) * so, (d0.y + bv.y) * so,
                                       (x1.y + bv.z) * so, (d1.y + bv.w) * so);
                *(float4*)&C[(size_t)(row + 1) * D + c0] = v;
            }
        }
    }
}

// ---------------- L5/L6: CSR propagation (unroll 4, half-warp per node) -----
template <bool POOL>
__global__ void prop_csr_kernel(const float4* __restrict__ xs,
                                float4* __restrict__ agg,
                                const float* __restrict__ scale,
                                const int* __restrict__ gid, int n) {
    int node = (blockIdx.x * blockDim.x + threadIdx.x) >> 4;
    int l = threadIdx.x & 15;
    if (node >= n) return;
    int b = g_off[node], e = g_off[node + 1];
    bool act = l < 14;
    bool dt  = (!POOL) && (l == 14);
    float4 a0 = make_float4(0.f, 0.f, 0.f, 0.f);
    float4 a1 = a0, a2 = a0, a3 = a0;
    float sd = 0.f;
    unsigned base = (unsigned)l;
    int k = b;
    for (; k + 4 <= e; k += 4) {
        int s0 = g_csr[k], s1 = g_csr[k + 1], s2 = g_csr[k + 2], s3 = g_csr[k + 3];
        if (act) {
            float4 v0 = xs[(unsigned)s0 * 14u + base];
            float4 v1 = xs[(unsigned)s1 * 14u + base];
            float4 v2 = xs[(unsigned)s2 * 14u + base];
            float4 v3 = xs[(unsigned)s3 * 14u + base];
            a0.x += v0.x; a0.y += v0.y; a0.z += v0.z; a0.w += v0.w;
            a1.x += v1.x; a1.y += v1.y; a1.z += v1.z; a1.w += v1.w;
            a2.x += v2.x; a2.y += v2.y; a2.z += v2.z; a2.w += v2.w;
            a3.x += v3.x; a3.y += v3.y; a3.z += v3.z; a3.w += v3.w;
        } else if (dt) {
            sd += g_inv_out[s0] + g_inv_out[s1] + g_inv_out[s2] + g_inv_out[s3];
        }
    }
    for (; k < e; k++) {
        int s0 = g_csr[k];
        if (act) {
            float4 v0 = xs[(unsigned)s0 * 14u + base];
            a0.x += v0.x; a0.y += v0.y; a0.z += v0.z; a0.w += v0.w;
        } else if (dt) {
            sd += g_inv_out[s0];
        }
    }
    if (act) {
        float sc = scale[node];
        float x = (a0.x + a1.x + a2.x + a3.x) * sc;
        float y = (a0.y + a1.y + a2.y + a3.y) * sc;
        float z = (a0.z + a1.z + a2.z + a3.z) * sc;
        float w = (a0.w + a1.w + a2.w + a3.w) * sc;
        if (!POOL) {
            agg[(unsigned)node * 14u + base] = make_float4(x, y, z, w);
        } else {
            float* poolX = g_zregion + ZR_POOLX;
            float* p = poolX + (unsigned)gid[node] * D + base * 4u;
            asm volatile("red.global.add.v4.f32 [%0], {%1,%2,%3,%4};"
                         :: "l"(p), "f"(x), "f"(y), "f"(z), "f"(w)
                         : "memory");
        }
    } else if (dt) {
        float* poolD = g_zregion + ZR_POOLD;
        atomicAdd(&poolD[gid[node]], sd * g_inv_in[node]);
    }
}

// ---------------- L7: final --------------------------------------------------
__global__ void final_kernel(float* __restrict__ out) {
    const float* poolX = g_zregion + ZR_POOLX;
    const float* poolD = g_zregion + ZR_POOLD;
    const float* cnt   = g_zregion + ZR_CNT;
    int g = blockIdx.x, tid = threadIdx.x;
    if (tid < NCLASS) {
        float invc = 1.0f / fmaxf(cnt[g], 1.0f);
        out[g * NCLASS + tid] = poolX[g * D + tid] * invc
                              + poolD[g] * invc * g_v1[tid]
                              + g_c0[tid];
    }
}

// ---------------- launch ---------------------------------------------------
extern "C" void kernel_launch(void* const* d_in, const int* in_sizes, int n_in,
                              void* d_out, int out_size) {
    const float* fsnet = (const float*)d_in[0];
    const int*   src   = (const int*)d_in[1];
    const int*   dst   = (const int*)d_in[2];
    const int*   gid   = (const int*)d_in[3];
    const float* W_ext = (const float*)d_in[4];
    const float* b_ext = (const float*)d_in[5];
    const float* W1    = (const float*)d_in[6];
    const float* b1    = (const float*)d_in[7];
    const float* W2    = (const float*)d_in[8];
    const float* b2    = (const float*)d_in[9];
    const float* Wc    = (const float*)d_in[10];
    const float* bc    = (const float*)d_in[11];
    float* out = (float*)d_out;

    int n   = in_sizes[3];
    int E   = in_sizes[1];
    int RAW = in_sizes[4] / LAT;

    float *bufA, *bufB, *inv_out, *inv_in, *s1, *wall, *bfold;
    cudaGetSymbolAddress((void**)&bufA,    g_bufA);
    cudaGetSymbolAddress((void**)&bufB,    g_bufB);
    cudaGetSymbolAddress((void**)&inv_out, g_inv_out);
    cudaGetSymbolAddress((void**)&inv_in,  g_inv_in);
    cudaGetSymbolAddress((void**)&s1,      g_s1);
    cudaGetSymbolAddress((void**)&wall,    g_Wall);
    cudaGetSymbolAddress((void**)&bfold,   g_bfold);

    cudaFuncSetAttribute(fuse_gemm_scatter_kernel,
                         cudaFuncAttributeMaxDynamicSharedMemorySize, GSMEM);

    int nb = (n + 1023) / 1024;          // scan blocks
    int eb = (E + 255) / 256;            // edge blocks (degree launch)
    int gb = (n + TM - 1) / TM;          // gemm blocks
    int ns = 148 * 3 - gb;               // co-resident scatter blocks
    if (ns < 16) ns = 16;
    if (ns > 148) ns = 148;

    // L1: zero packed scratch + lookback state
    prep_kernel<<<148, 256>>>();
    // L2: degree histograms || T1 = W2@Wc
    fuse_deg_wT_kernel<<<WT_BLK + eb, 256>>>(src, dst, E, W2, Wc);
    // L3: single-pass scan || Wfin || Wall || biases (flag-ordered)
    fuse_scan_fold_kernel<<<SCAN_BASE + nb, 1024>>>(
        gid, n, nb, W1, W_ext, RAW, b1, b2, Wc, bc, b_ext);
    // L4: persistent scatter blocks || GEMM0 (all co-resident in wave 1)
    fuse_gemm_scatter_kernel<<<ns + gb, 256, GSMEM>>>(
        fsnet, wall, bfold, inv_out, bufA, n, RAW, ns, src, dst, E);
    // L5: prop1 (+ fused dtilde): bufB = P(z0) * s1
    int pblocks = (n * 16 + 255) / 256;
    prop_csr_kernel<false><<<pblocks, 256>>>((const float4*)bufA, (float4*)bufB, s1, gid, n);
    // L6: prop2 fused with graph pooling
    prop_csr_kernel<true><<<pblocks, 256>>>((const float4*)bufB, nullptr, inv_in, gid, n);
    // L7: out = poolX/cnt + (poolD/cnt)*v1 + c0
    final_kernel<<<NGRAPH, 64>>>(out);
}